// round 1
// baseline (speedup 1.0000x reference)
#include <cuda_runtime.h>
#include <cuda_bf16.h>
#include <math.h>

// Problem constants
#define BB   256
#define LL   512
#define TT   (BB*LL)     // 131072 tokens
#define DD   256
#define DIi  512         // E*D
#define DSs  16
#define DCc  4
#define DTRr 16
#define NLl  2
#define NXP  48          // DTR + 2*DS
#define DH   128         // D/2

// Scratch (static __device__, no allocation allowed)
__device__ float g_h[(size_t)TT*DD];        // residual stream [T, D]
__device__ float g_xraw[(size_t)TT*DIi];    // pre-conv xs; reused as scan output y
__device__ float g_xs[(size_t)TT*DIi];      // post-conv silu xs (u in scan)
__device__ float g_r[(size_t)TT*DIi];       // gate r
__device__ float g_dbl[(size_t)TT*NXP];     // [dt(16) | B(16) | C(16)]
__device__ float g_delta[(size_t)TT*DIi];   // softplus delta
__device__ float g_stats[(size_t)TT*2];     // mu, rsig per (b,l)
__device__ float g_p[BB*DD];                // pooled LN output

// -------------------- embedding --------------------
__global__ void embed_k(const int* __restrict__ x, const float* __restrict__ emb) {
    int idx = blockIdx.x * blockDim.x + threadIdx.x;   // < TT*DD
    int t = idx >> 8;
    int d = idx & 255;
    g_h[idx] = emb[x[t]*DD + d];
}

// -------------------- tiled fp32 GEMM --------------------
// C[M,N] = A[M,K] @ Bw[K,N] (+bias) with mode-specific source/dest:
//   mode 0: A=g_h,    out split: cols<DIi -> g_xraw, cols>=DIi -> g_r  (in_proj)
//   mode 1: A=g_xraw, out = acc + bias + g_h -> g_h (in place residual) (out_proj)
//   mode 2: A=g_xs,   out -> g_dbl (N=48, no bias)                      (x_proj)
#define BM 128
#define BN 64
#define BK 16

__global__ __launch_bounds__(256) void gemm_k(
    const float* __restrict__ Bw, const float* __restrict__ bias,
    int M, int N, int K, int mode)
{
    const float* A = (mode == 0) ? g_h : (mode == 1) ? g_xraw : g_xs;

    __shared__ float As[BK][BM];
    __shared__ float Bs[BK][BN];

    int tid = threadIdx.x;
    int bm = blockIdx.y * BM;
    int bn = blockIdx.x * BN;
    int tx = tid & 15;    // N dir: 16 * 4
    int ty = tid >> 4;    // M dir: 16 * 8

    float acc[8][4];
    #pragma unroll
    for (int i = 0; i < 8; i++)
        #pragma unroll
        for (int j = 0; j < 4; j++) acc[i][j] = 0.f;

    for (int kt = 0; kt < K; kt += BK) {
        // A tile: 128 rows x 16 k, float4 loads, store transposed
        #pragma unroll
        for (int i = 0; i < 2; i++) {
            int idx = tid + i*256;          // 0..511 (float4 granules)
            int row = idx >> 2;
            int k4  = (idx & 3) << 2;
            float4 v = *(const float4*)(A + (size_t)(bm + row)*K + kt + k4);
            As[k4+0][row] = v.x; As[k4+1][row] = v.y;
            As[k4+2][row] = v.z; As[k4+3][row] = v.w;
        }
        // B tile: 16 rows x 64 cols, scalar guarded (N may be 48)
        #pragma unroll
        for (int i = 0; i < 4; i++) {
            int idx = tid + i*256;          // 0..1023
            int row = idx >> 6;
            int col = idx & 63;
            float v = 0.f;
            if (bn + col < N) v = Bw[(size_t)(kt + row)*N + bn + col];
            Bs[row][col] = v;
        }
        __syncthreads();

        #pragma unroll
        for (int k = 0; k < BK; k++) {
            float a[8], b[4];
            #pragma unroll
            for (int i = 0; i < 8; i++) a[i] = As[k][ty*8 + i];
            #pragma unroll
            for (int j = 0; j < 4; j++) b[j] = Bs[k][tx*4 + j];
            #pragma unroll
            for (int i = 0; i < 8; i++)
                #pragma unroll
                for (int j = 0; j < 4; j++) acc[i][j] += a[i]*b[j];
        }
        __syncthreads();
    }

    #pragma unroll
    for (int i = 0; i < 8; i++) {
        int gm = bm + ty*8 + i;
        #pragma unroll
        for (int j = 0; j < 4; j++) {
            int gn = bn + tx*4 + j;
            if (gn >= N) continue;
            float v = acc[i][j];
            if (bias) v += bias[gn];
            if (mode == 0) {
                if (gn < DIi) g_xraw[(size_t)gm*DIi + gn] = v;
                else          g_r[(size_t)gm*DIi + gn - DIi] = v;
            } else if (mode == 1) {
                g_h[(size_t)gm*DD + gn] = v + g_h[(size_t)gm*DD + gn];
            } else {
                g_dbl[(size_t)gm*NXP + gn] = v;
            }
        }
    }
}

// -------------------- causal depthwise conv (k=4) + silu --------------------
__global__ void conv_silu_k(const float* __restrict__ cw, const float* __restrict__ cb) {
    int idx = blockIdx.x * blockDim.x + threadIdx.x;   // < TT*DIi
    int d = idx & (DIi - 1);
    int t = idx >> 9;
    int l = t & (LL - 1);
    float acc = cb[d];
    #pragma unroll
    for (int j = 0; j < DCc; j++) {
        int lj = l + j - (DCc - 1);
        if (lj >= 0)
            acc += g_xraw[(size_t)(t + j - (DCc - 1))*DIi + d] * cw[d*DCc + j];
    }
    g_xs[idx] = acc / (1.f + __expf(-acc));
}

// -------------------- delta = softplus(dt @ dt_w + dt_b) --------------------
__global__ __launch_bounds__(128) void delta_k(const float* __restrict__ dtw,
                                               const float* __restrict__ dtb) {
    int t = blockIdx.x;
    __shared__ float sdt[DTRr];
    if (threadIdx.x < DTRr) sdt[threadIdx.x] = g_dbl[(size_t)t*NXP + threadIdx.x];
    __syncthreads();
    #pragma unroll
    for (int jj = 0; jj < 4; jj++) {
        int d = threadIdx.x + jj*128;
        float xv = dtb[d];
        #pragma unroll
        for (int r2 = 0; r2 < DTRr; r2++) xv += sdt[r2]*dtw[r2*DIi + d];
        float sp = fmaxf(xv, 0.f) + log1pf(__expf(-fabsf(xv)));
        g_delta[(size_t)t*DIi + d] = sp;
    }
}

// -------------------- selective scan (fused with D*u, silu(r) gate) --------------------
__global__ __launch_bounds__(128) void scan_k(const float* __restrict__ Alog,
                                              const float* __restrict__ Dp) {
    int b = blockIdx.x >> 2;
    int d = ((blockIdx.x & 3) << 7) + threadIdx.x;
    float Av[DSs], hs[DSs];
    #pragma unroll
    for (int s = 0; s < DSs; s++) {
        Av[s] = -__expf(Alog[d*DSs + s]);
        hs[s] = 0.f;
    }
    float Dd = Dp[d];
    __shared__ float sBC[32];
    int tbase = b*LL;
    for (int l = 0; l < LL; l++) {
        int t = tbase + l;
        if (threadIdx.x < 32) sBC[threadIdx.x] = g_dbl[(size_t)t*NXP + DTRr + threadIdx.x];
        __syncthreads();
        float dlt = g_delta[(size_t)t*DIi + d];
        float u   = g_xs[(size_t)t*DIi + d];
        float du = dlt*u;
        float y = 0.f;
        #pragma unroll
        for (int s = 0; s < DSs; s++) {
            float e = __expf(dlt*Av[s]);
            hs[s] = e*hs[s] + du*sBC[s];
            y += hs[s]*sBC[16 + s];
        }
        float rr = g_r[(size_t)t*DIi + d];
        float sr = rr / (1.f + __expf(-rr));
        g_xraw[(size_t)t*DIi + d] = (y + u*Dd)*sr;
        __syncthreads();
    }
}

// -------------------- LayerNorm stats per (b,l) row --------------------
__global__ __launch_bounds__(256) void ln_stats_k() {
    int t = blockIdx.x;
    int tid = threadIdx.x;
    float v = g_h[(size_t)t*DD + tid];
    float s = v, q = v*v;
    #pragma unroll
    for (int o = 16; o > 0; o >>= 1) {
        s += __shfl_down_sync(0xffffffffu, s, o);
        q += __shfl_down_sync(0xffffffffu, q, o);
    }
    __shared__ float ws[8], wq[8];
    int wid = tid >> 5, lane = tid & 31;
    if (lane == 0) { ws[wid] = s; wq[wid] = q; }
    __syncthreads();
    if (tid == 0) {
        float S = 0.f, Q = 0.f;
        #pragma unroll
        for (int i = 0; i < 8; i++) { S += ws[i]; Q += wq[i]; }
        float mu = S * (1.f/DD);
        float var = Q * (1.f/DD) - mu*mu;
        g_stats[t*2]     = mu;
        g_stats[t*2 + 1] = rsqrtf(var + 1e-5f);
    }
}

// -------------------- mean over L of LN output --------------------
__global__ __launch_bounds__(256) void pmean_k(const float* __restrict__ g,
                                               const float* __restrict__ bln) {
    int b = blockIdx.x;
    int d = threadIdx.x;
    float acc = 0.f;
    for (int l = 0; l < LL; l++) {
        int t = b*LL + l;
        acc += (g_h[(size_t)t*DD + d] - g_stats[t*2]) * g_stats[t*2 + 1];
    }
    g_p[b*DD + d] = g[d]*acc*(1.f/LL) + bln[d];
}

// -------------------- MLP head --------------------
__global__ __launch_bounds__(128) void head_k(const float* __restrict__ w1,
                                              const float* __restrict__ b1,
                                              const float* __restrict__ w2,
                                              const float* __restrict__ b2,
                                              float* __restrict__ out) {
    int b = blockIdx.x;
    int j = threadIdx.x;
    float hsum = b1[j];
    #pragma unroll 8
    for (int d = 0; d < DD; d++) hsum += g_p[b*DD + d]*w1[d*DH + j];
    hsum = fmaxf(hsum, 0.f);
    __shared__ float s0[DH], s1[DH];
    s0[j] = hsum*w2[j*2];
    s1[j] = hsum*w2[j*2 + 1];
    __syncthreads();
    #pragma unroll
    for (int st = 64; st > 0; st >>= 1) {
        if (j < st) { s0[j] += s0[j + st]; s1[j] += s1[j + st]; }
        __syncthreads();
    }
    if (j == 0) {
        out[b*2]     = s0[0] + b2[0];
        out[b*2 + 1] = s1[0] + b2[1];
    }
}

// -------------------- launcher --------------------
extern "C" void kernel_launch(void* const* d_in, const int* in_sizes, int n_in,
                              void* d_out, int out_size) {
    const int*   x       = (const int*)  d_in[0];
    const float* emb     = (const float*)d_in[1];
    const float* in_w    = (const float*)d_in[2];
    const float* in_b    = (const float*)d_in[3];
    const float* conv_w  = (const float*)d_in[4];
    const float* conv_b  = (const float*)d_in[5];
    const float* xproj_w = (const float*)d_in[6];
    const float* dt_w    = (const float*)d_in[7];
    const float* dt_b    = (const float*)d_in[8];
    const float* A_log   = (const float*)d_in[9];
    const float* Dp      = (const float*)d_in[10];
    const float* out_w   = (const float*)d_in[11];
    const float* out_b   = (const float*)d_in[12];
    const float* ln_g    = (const float*)d_in[13];
    const float* ln_b    = (const float*)d_in[14];
    const float* w1      = (const float*)d_in[15];
    const float* b1      = (const float*)d_in[16];
    const float* w2      = (const float*)d_in[17];
    const float* b2      = (const float*)d_in[18];
    float* out = (float*)d_out;

    embed_k<<<(TT*DD)/256, 256>>>(x, emb);

    for (int l = 0; l < NLl; l++) {
        // in_proj: [T,256] @ [256,1024] -> xraw | r
        gemm_k<<<dim3((2*DIi)/BN, TT/BM), 256>>>(
            in_w + (size_t)l*DD*2*DIi, in_b + (size_t)l*2*DIi, TT, 2*DIi, DD, 0);
        // causal depthwise conv + silu
        conv_silu_k<<<(TT*DIi)/256, 256>>>(conv_w + (size_t)l*DIi*DCc, conv_b + (size_t)l*DIi);
        // x_proj: [T,512] @ [512,48] -> dbl
        gemm_k<<<dim3(1, TT/BM), 256>>>(
            xproj_w + (size_t)l*DIi*NXP, nullptr, TT, NXP, DIi, 2);
        // delta
        delta_k<<<TT, 128>>>(dt_w + (size_t)l*DTRr*DIi, dt_b + (size_t)l*DIi);
        // selective scan + gate
        scan_k<<<BB*4, 128>>>(A_log + (size_t)l*DIi*DSs, Dp + (size_t)l*DIi);
        // out_proj + residual (in place on g_h)
        gemm_k<<<dim3(DD/BN, TT/BM), 256>>>(
            out_w + (size_t)l*DIi*DD, out_b + (size_t)l*DD, TT, DD, DIi, 1);
    }

    ln_stats_k<<<TT, 256>>>();
    pmean_k<<<BB, DD>>>(ln_g, ln_b);
    head_k<<<BB, DH>>>(w1, b1, w2, b2, out);
}

// round 4
// speedup vs baseline: 1.0931x; 1.0931x over previous
#include <cuda_runtime.h>
#include <cuda_bf16.h>
#include <math.h>

// Problem constants
#define BB   256
#define LL   512
#define TT   (BB*LL)     // 131072 tokens
#define DD   256
#define DIi  512         // E*D
#define DSs  16
#define DCc  4
#define DTRr 16
#define NLl  2
#define NXP  48          // DTR + 2*DS
#define DH   128         // D/2

// Scratch (static __device__, no allocation allowed)
__device__ float g_h[(size_t)TT*DD];        // residual stream [T, D]
__device__ float g_xraw[(size_t)TT*DIi];    // pre-conv xs; reused as scan output y
__device__ float g_xs[(size_t)TT*DIi];      // post-conv silu xs (u in scan)
__device__ float g_r[(size_t)TT*DIi];       // gate r
__device__ float g_dbl[(size_t)TT*NXP];     // [dt(16) | B(16) | C(16)]
__device__ float g_p[BB*DD];                // pooled LN output

// -------------------- embedding --------------------
__global__ void embed_k(const int* __restrict__ x, const float* __restrict__ emb) {
    int idx = blockIdx.x * blockDim.x + threadIdx.x;   // < TT*DD
    int t = idx >> 8;
    int d = idx & 255;
    g_h[idx] = emb[x[t]*DD + d];
}

// -------------------- 128x128x16 fp32 GEMM, 8x8 microtile --------------------
//   mode 0: A=g_h,    out split: cols<DIi -> g_xraw, cols>=DIi -> g_r  (in_proj)
//   mode 1: A=g_xraw, out = acc + bias + g_h -> g_h (residual)          (out_proj)
//   mode 2: A=g_xs,   out -> g_dbl (N=48, no bias)                      (x_proj)
#define BM 128
#define BN 128
#define BK 16

__global__ __launch_bounds__(256, 2) void gemm2_k(
    const float* __restrict__ Bw, const float* __restrict__ bias,
    int M, int N, int K, int mode)
{
    const float* A = (mode == 0) ? g_h : (mode == 1) ? g_xraw : g_xs;

    __shared__ float As[BK][BM];
    __shared__ float Bs[BK][BN];

    int tid = threadIdx.x;
    int bm = blockIdx.y * BM;
    int bn = blockIdx.x * BN;
    int tx = tid & 15;    // N dir
    int ty = tid >> 4;    // M dir

    // Global-load addressing (512 float4 granules per tile, 2 per thread)
    int arow = tid >> 2;             // 0..63 (second granule: +64)
    int akq  = (tid & 3) << 2;       // k offset 0,4,8,12
    int brow = tid >> 5;             // 0..7 (second granule: +8)
    int bc   = (tid & 31) << 2;      // col offset 0..124

    float acc[8][8];
    #pragma unroll
    for (int i = 0; i < 8; i++)
        #pragma unroll
        for (int j = 0; j < 8; j++) acc[i][j] = 0.f;

    float4 a0, a1, b0, b1;

    // prologue loads for kt=0
    {
        a0 = *(const float4*)(A + (size_t)(bm + arow)*K + akq);
        a1 = *(const float4*)(A + (size_t)(bm + arow + 64)*K + akq);
        if (bn + bc + 4 <= N) b0 = *(const float4*)(Bw + (size_t)(brow)*N + bn + bc);
        else b0 = make_float4(0.f,0.f,0.f,0.f);
        if (bn + bc + 4 <= N) b1 = *(const float4*)(Bw + (size_t)(brow + 8)*N + bn + bc);
        else b1 = make_float4(0.f,0.f,0.f,0.f);
    }

    for (int kt = 0; kt < K; kt += BK) {
        // store staged tile to smem (A transposed)
        As[akq+0][arow] = a0.x; As[akq+1][arow] = a0.y;
        As[akq+2][arow] = a0.z; As[akq+3][arow] = a0.w;
        As[akq+0][arow+64] = a1.x; As[akq+1][arow+64] = a1.y;
        As[akq+2][arow+64] = a1.z; As[akq+3][arow+64] = a1.w;
        *(float4*)&Bs[brow][bc]   = b0;
        *(float4*)&Bs[brow+8][bc] = b1;
        __syncthreads();

        // prefetch next tile
        int kn = kt + BK;
        if (kn < K) {
            a0 = *(const float4*)(A + (size_t)(bm + arow)*K + kn + akq);
            a1 = *(const float4*)(A + (size_t)(bm + arow + 64)*K + kn + akq);
            if (bn + bc + 4 <= N) b0 = *(const float4*)(Bw + (size_t)(kn + brow)*N + bn + bc);
            else b0 = make_float4(0.f,0.f,0.f,0.f);
            if (bn + bc + 4 <= N) b1 = *(const float4*)(Bw + (size_t)(kn + brow + 8)*N + bn + bc);
            else b1 = make_float4(0.f,0.f,0.f,0.f);
        }

        #pragma unroll
        for (int k = 0; k < BK; k++) {
            float4 af0 = *(const float4*)&As[k][ty*8];
            float4 af1 = *(const float4*)&As[k][ty*8 + 4];
            float4 bf0 = *(const float4*)&Bs[k][tx*8];
            float4 bf1 = *(const float4*)&Bs[k][tx*8 + 4];
            float av[8] = {af0.x, af0.y, af0.z, af0.w, af1.x, af1.y, af1.z, af1.w};
            float bv[8] = {bf0.x, bf0.y, bf0.z, bf0.w, bf1.x, bf1.y, bf1.z, bf1.w};
            #pragma unroll
            for (int i = 0; i < 8; i++)
                #pragma unroll
                for (int j = 0; j < 8; j++) acc[i][j] += av[i]*bv[j];
        }
        __syncthreads();
    }

    // epilogue
    int gn0 = bn + tx*8;
    #pragma unroll
    for (int i = 0; i < 8; i++) {
        int gm = bm + ty*8 + i;
        if (mode == 0) {
            float4 v0 = make_float4(acc[i][0]+bias[gn0+0], acc[i][1]+bias[gn0+1],
                                    acc[i][2]+bias[gn0+2], acc[i][3]+bias[gn0+3]);
            float4 v1 = make_float4(acc[i][4]+bias[gn0+4], acc[i][5]+bias[gn0+5],
                                    acc[i][6]+bias[gn0+6], acc[i][7]+bias[gn0+7]);
            if (gn0 < DIi) {
                *(float4*)(g_xraw + (size_t)gm*DIi + gn0)     = v0;
                *(float4*)(g_xraw + (size_t)gm*DIi + gn0 + 4) = v1;
            } else {
                *(float4*)(g_r + (size_t)gm*DIi + gn0 - DIi)     = v0;
                *(float4*)(g_r + (size_t)gm*DIi + gn0 - DIi + 4) = v1;
            }
        } else if (mode == 1) {
            float4 h0 = *(const float4*)(g_h + (size_t)gm*DD + gn0);
            float4 h1 = *(const float4*)(g_h + (size_t)gm*DD + gn0 + 4);
            h0.x += acc[i][0]+bias[gn0+0]; h0.y += acc[i][1]+bias[gn0+1];
            h0.z += acc[i][2]+bias[gn0+2]; h0.w += acc[i][3]+bias[gn0+3];
            h1.x += acc[i][4]+bias[gn0+4]; h1.y += acc[i][5]+bias[gn0+5];
            h1.z += acc[i][6]+bias[gn0+6]; h1.w += acc[i][7]+bias[gn0+7];
            *(float4*)(g_h + (size_t)gm*DD + gn0)     = h0;
            *(float4*)(g_h + (size_t)gm*DD + gn0 + 4) = h1;
        } else {
            #pragma unroll
            for (int j = 0; j < 8; j++) {
                int gn = gn0 + j;
                if (gn < N) g_dbl[(size_t)gm*NXP + gn] = acc[i][j];
            }
        }
    }
}

// -------------------- causal depthwise conv (k=4) + silu --------------------
__global__ void conv_silu_k(const float* __restrict__ cw, const float* __restrict__ cb) {
    int idx = blockIdx.x * blockDim.x + threadIdx.x;   // < TT*DIi
    int d = idx & (DIi - 1);
    int t = idx >> 9;
    int l = t & (LL - 1);
    float acc = cb[d];
    #pragma unroll
    for (int j = 0; j < DCc; j++) {
        int lj = l + j - (DCc - 1);
        if (lj >= 0)
            acc += g_xraw[(size_t)(t + j - (DCc - 1))*DIi + d] * cw[d*DCc + j];
    }
    g_xs[idx] = acc / (1.f + __expf(-acc));
}

// ------- selective scan, fused: delta=softplus(dt@dt_w+dt_b), D*u, silu(r) gate -------
__global__ __launch_bounds__(128) void scan_k(const float* __restrict__ Alog,
                                              const float* __restrict__ Dp,
                                              const float* __restrict__ dtw,
                                              const float* __restrict__ dtb) {
    int b = blockIdx.x >> 2;
    int d = ((blockIdx.x & 3) << 7) + threadIdx.x;

    float Av[DSs];
    bool ia = true;   // A[s] == -(s+1)? then exp(dlt*A_s) = p^(s+1), p=exp(-dlt)
    #pragma unroll
    for (int s = 0; s < DSs; s++) {
        Av[s] = -__expf(Alog[d*DSs + s]);
        ia = ia && (fabsf(Av[s] + (float)(s+1)) < 1e-4f);
    }
    float wr[DTRr];
    #pragma unroll
    for (int r2 = 0; r2 < DTRr; r2++) wr[r2] = dtw[r2*DIi + d];
    float dtb_d = dtb[d];
    float Dd = Dp[d];

    float hs[DSs];
    #pragma unroll
    for (int s = 0; s < DSs; s++) hs[s] = 0.f;

    size_t tb = (size_t)b*LL;
    float u_n = g_xs[tb*DIi + d];
    float r_n = g_r [tb*DIi + d];

    for (int l = 0; l < LL; l++) {
        size_t t = tb + l;
        float u  = u_n;
        float rr = r_n;
        if (l + 1 < LL) {
            u_n = g_xs[(t+1)*DIi + d];
            r_n = g_r [(t+1)*DIi + d];
        }
        // uniform load of the dbl row: dt(16) | B(16) | C(16)
        union { float4 v[12]; float f[48]; } q;
        const float4* qp = (const float4*)(g_dbl + t*NXP);
        #pragma unroll
        for (int i = 0; i < 12; i++) q.v[i] = qp[i];

        // delta = softplus(dt @ dt_w + dt_b)
        float xv = dtb_d;
        #pragma unroll
        for (int r2 = 0; r2 < DTRr; r2++) xv += q.f[r2]*wr[r2];
        float dlt = fmaxf(xv, 0.f) + __logf(1.f + __expf(-fabsf(xv)));
        float du = dlt*u;

        float e[DSs];
        if (ia) {
            float p = __expf(-dlt);
            e[0] = p;
            #pragma unroll
            for (int s = 1; s < DSs; s++) e[s] = e[s>>1]*e[(s-1)>>1];  // p^(s+1)
        } else {
            #pragma unroll
            for (int s = 0; s < DSs; s++) e[s] = __expf(dlt*Av[s]);
        }

        float y = 0.f;
        #pragma unroll
        for (int s = 0; s < DSs; s++) {
            hs[s] = e[s]*hs[s] + du*q.f[16 + s];
            y += hs[s]*q.f[32 + s];
        }
        float sg = rr / (1.f + __expf(-rr));
        g_xraw[t*DIi + d] = (y + u*Dd)*sg;
    }
}

// -------------------- fused LayerNorm + mean-pool over L --------------------
__global__ __launch_bounds__(256) void lnpool_k(const float* __restrict__ g,
                                                const float* __restrict__ bln) {
    int b = blockIdx.x;
    int d = threadIdx.x;
    int wid = d >> 5, lane = d & 31;
    __shared__ float ws[8], wq[8];
    float acc = 0.f;
    for (int l = 0; l < LL; l++) {
        size_t t = (size_t)b*LL + l;
        float v = g_h[t*DD + d];
        float s = v, qq = v*v;
        #pragma unroll
        for (int o = 16; o > 0; o >>= 1) {
            s  += __shfl_down_sync(0xffffffffu, s, o);
            qq += __shfl_down_sync(0xffffffffu, qq, o);
        }
        if (lane == 0) { ws[wid] = s; wq[wid] = qq; }
        __syncthreads();
        float S = 0.f, Q = 0.f;
        #pragma unroll
        for (int i = 0; i < 8; i++) { S += ws[i]; Q += wq[i]; }
        float mu = S * (1.f/DD);
        float var = Q * (1.f/DD) - mu*mu;
        acc += (v - mu) * rsqrtf(var + 1e-5f);
        __syncthreads();
    }
    g_p[b*DD + d] = g[d]*acc*(1.f/LL) + bln[d];
}

// -------------------- MLP head --------------------
__global__ __launch_bounds__(128) void head_k(const float* __restrict__ w1,
                                              const float* __restrict__ b1,
                                              const float* __restrict__ w2,
                                              const float* __restrict__ b2,
                                              float* __restrict__ out) {
    int b = blockIdx.x;
    int j = threadIdx.x;
    float hsum = b1[j];
    #pragma unroll 8
    for (int d = 0; d < DD; d++) hsum += g_p[b*DD + d]*w1[d*DH + j];
    hsum = fmaxf(hsum, 0.f);
    __shared__ float s0[DH], s1[DH];
    s0[j] = hsum*w2[j*2];
    s1[j] = hsum*w2[j*2 + 1];
    __syncthreads();
    #pragma unroll
    for (int st = 64; st > 0; st >>= 1) {
        if (j < st) { s0[j] += s0[j + st]; s1[j] += s1[j + st]; }
        __syncthreads();
    }
    if (j == 0) {
        out[b*2]     = s0[0] + b2[0];
        out[b*2 + 1] = s1[0] + b2[1];
    }
}

// -------------------- launcher --------------------
extern "C" void kernel_launch(void* const* d_in, const int* in_sizes, int n_in,
                              void* d_out, int out_size) {
    const int*   x       = (const int*)  d_in[0];
    const float* emb     = (const float*)d_in[1];
    const float* in_w    = (const float*)d_in[2];
    const float* in_b    = (const float*)d_in[3];
    const float* conv_w  = (const float*)d_in[4];
    const float* conv_b  = (const float*)d_in[5];
    const float* xproj_w = (const float*)d_in[6];
    const float* dt_w    = (const float*)d_in[7];
    const float* dt_b    = (const float*)d_in[8];
    const float* A_log   = (const float*)d_in[9];
    const float* Dp      = (const float*)d_in[10];
    const float* out_w   = (const float*)d_in[11];
    const float* out_b   = (const float*)d_in[12];
    const float* ln_g    = (const float*)d_in[13];
    const float* ln_b    = (const float*)d_in[14];
    const float* w1      = (const float*)d_in[15];
    const float* b1      = (const float*)d_in[16];
    const float* w2      = (const float*)d_in[17];
    const float* b2      = (const float*)d_in[18];
    float* out = (float*)d_out;

    embed_k<<<(TT*DD)/256, 256>>>(x, emb);

    for (int l = 0; l < NLl; l++) {
        // in_proj: [T,256] @ [256,1024] -> xraw | r
        gemm2_k<<<dim3((2*DIi)/BN, TT/BM), 256>>>(
            in_w + (size_t)l*DD*2*DIi, in_b + (size_t)l*2*DIi, TT, 2*DIi, DD, 0);
        // causal depthwise conv + silu
        conv_silu_k<<<(TT*DIi)/256, 256>>>(conv_w + (size_t)l*DIi*DCc, conv_b + (size_t)l*DIi);
        // x_proj: [T,512] @ [512,48] -> dbl
        gemm2_k<<<dim3(1, TT/BM), 256>>>(
            xproj_w + (size_t)l*DIi*NXP, nullptr, TT, NXP, DIi, 2);
        // selective scan (fused delta + D*u + silu gate)
        scan_k<<<BB*4, 128>>>(A_log + (size_t)l*DIi*DSs, Dp + (size_t)l*DIi,
                              dt_w + (size_t)l*DTRr*DIi, dt_b + (size_t)l*DIi);
        // out_proj + residual (in place on g_h)
        gemm2_k<<<dim3(DD/BN, TT/BM), 256>>>(
            out_w + (size_t)l*DIi*DD, out_b + (size_t)l*DD, TT, DD, DIi, 1);
    }

    lnpool_k<<<BB, 256>>>(ln_g, ln_b);
    head_k<<<BB, DH>>>(w1, b1, w2, b2, out);
}

// round 10
// speedup vs baseline: 1.9230x; 1.7593x over previous
#include <cuda_runtime.h>
#include <cuda_bf16.h>
#include <math.h>
#include <stdint.h>

// Problem constants
#define BB   256
#define LL   512
#define TT   (BB*LL)     // 131072 tokens
#define DD   256
#define DIi  512
#define DSs  16
#define DCc  4
#define DTRr 16
#define NLl  2
#define NXP  48
#define DH   128
#define APITCH 40        // smem row pitch in bf16 elems (80B): conflict-free ldmatrix

// ---------------- scratch (static, no allocation) ----------------
__device__ float g_h[(size_t)TT*DD];        // residual stream fp32
__device__ float g_xraw[(size_t)TT*DIi];    // in_proj xs output (conv input)
__device__ float g_xs[(size_t)TT*DIi];      // post-conv silu (scan u)
__device__ float g_r[(size_t)TT*DIi];       // gate r
__device__ float g_dbl[(size_t)TT*NXP];     // dt|B|C
__device__ float g_p[BB*DD];
__device__ float g_vt[64*1024];             // vocab table for layer-0 in_proj
// bf16 hi/lo activation planes (GEMM A operands)
__device__ __nv_bfloat16 g_hh[(size_t)TT*DD],  g_hl[(size_t)TT*DD];    // h split (in_proj L1)
__device__ __nv_bfloat16 g_xrh[(size_t)TT*DIi], g_xrl[(size_t)TT*DIi]; // scan y split (out_proj)
__device__ __nv_bfloat16 g_xsh[(size_t)TT*DIi], g_xsl[(size_t)TT*DIi]; // xs split (x_proj)
// bf16 hi/lo weights, K-major [Npad][K]: in[1024][256] | xp[128][512] | out[256][512]
#define WT_IN   0
#define WT_XP   262144
#define WT_OUT  327680
#define WT_LAY  458752
__device__ __nv_bfloat16 g_wbh[2*WT_LAY], g_wbl[2*WT_LAY];

// ---------------- PTX helpers (arch-agnostic: sm_80-era only) ----------------
__device__ __forceinline__ uint32_t smem_u32(const void* p) {
    uint32_t a;
    asm("{ .reg .u64 t; cvta.to.shared.u64 t, %1; cvt.u32.u64 %0, t; }" : "=r"(a) : "l"(p));
    return a;
}
__device__ __forceinline__ void cpa16(uint32_t dst, const void* src) {
    asm volatile("cp.async.cg.shared.global [%0], [%1], 16;" :: "r"(dst), "l"(src));
}
__device__ __forceinline__ void cpa_wait() {
    asm volatile("cp.async.commit_group;\ncp.async.wait_group 0;" ::: "memory");
}
__device__ __forceinline__ void ldsm4(uint32_t* r, uint32_t addr) {
    asm volatile("ldmatrix.sync.aligned.m8n8.x4.shared.b16 {%0,%1,%2,%3}, [%4];"
        : "=r"(r[0]), "=r"(r[1]), "=r"(r[2]), "=r"(r[3]) : "r"(addr));
}
__device__ __forceinline__ void mma16816(float* d, const uint32_t* a, const uint32_t* b) {
    asm volatile(
        "mma.sync.aligned.m16n8k16.row.col.f32.bf16.bf16.f32 "
        "{%0,%1,%2,%3}, {%4,%5,%6,%7}, {%8,%9}, {%0,%1,%2,%3};"
        : "+f"(d[0]), "+f"(d[1]), "+f"(d[2]), "+f"(d[3])
        : "r"(a[0]), "r"(a[1]), "r"(a[2]), "r"(a[3]), "r"(b[0]), "r"(b[1]));
}

// ---------------- embedding ----------------
__global__ void embed_k(const int* __restrict__ x, const float* __restrict__ emb) {
    int idx = blockIdx.x * blockDim.x + threadIdx.x;
    int t = idx >> 8, d = idx & 255;
    g_h[idx] = emb[x[t]*DD + d];
}

// ---------------- vocab table: VT = emb @ in_w0 + in_b0 ----------------
__global__ __launch_bounds__(256) void vt_k(const float* __restrict__ emb,
                                            const float* __restrict__ w,
                                            const float* __restrict__ b) {
    __shared__ float se[DD];
    int v = blockIdx.x;
    for (int i = threadIdx.x; i < DD; i += 256) se[i] = emb[v*DD + i];
    __syncthreads();
    #pragma unroll
    for (int jj = 0; jj < 4; jj++) {
        int col = threadIdx.x + jj*256;
        float acc = b[col];
        for (int k = 0; k < DD; k++) acc += se[k]*w[(size_t)k*1024 + col];
        g_vt[v*1024 + col] = acc;
    }
}

// ---------------- layer-0 in_proj = gather from VT ----------------
__global__ void gather_k(const int* __restrict__ x) {
    int idx = blockIdx.x * blockDim.x + threadIdx.x;   // TT*128
    int t = idx >> 7, q = (idx & 127) << 2;
    int v = x[t];
    float4 a = *(const float4*)(g_vt + v*1024 + q);
    float4 bb = *(const float4*)(g_vt + v*1024 + 512 + q);
    *(float4*)(g_xraw + (size_t)t*DIi + q) = a;
    *(float4*)(g_r    + (size_t)t*DIi + q) = bb;
}

// ---------------- weight transpose + bf16 hi/lo split ----------------
// dst[n*K+k] = (n<N)? src[k*N+n] : 0
__global__ void tsplit_k(const float* __restrict__ src, __nv_bfloat16* __restrict__ dh,
                         __nv_bfloat16* __restrict__ dl, int N, int kshift) {
    int idx = blockIdx.x * blockDim.x + threadIdx.x;
    int K = 1 << kshift;
    int k = idx & (K - 1), n = idx >> kshift;
    float v = (n < N) ? src[(size_t)k*N + n] : 0.f;
    __nv_bfloat16 h = __float2bfloat16_rn(v);
    dh[idx] = h;
    dl[idx] = __float2bfloat16_rn(v - __bfloat162float(h));
}

// ---------------- bf16-split mma.sync GEMM ----------------
// D[128 x 128-block] = A[.,K] @ W[Npad,K]^T, 3-product compensation, fp32 accum.
// MODE 0: A = g_hh/g_hl   -> g_xraw | g_r (+bias)   (in_proj L1, K=256)
// MODE 1: A = g_xrh/g_xrl -> g_h += (+bias), + h split (out_proj, K=512)
// MODE 2: A = g_xsh/g_xsl -> g_dbl cols<48          (x_proj, K=512)
template<int MODE, int K>
__global__ __launch_bounds__(256, 2) void mmagemm_k(const __nv_bfloat16* __restrict__ Wh,
                                                    const __nv_bfloat16* __restrict__ Wl,
                                                    const float* __restrict__ bias) {
    __shared__ __nv_bfloat16 sAh[128*APITCH], sAl[128*APITCH];
    __shared__ __nv_bfloat16 sBh[128*APITCH], sBl[128*APITCH];

    const __nv_bfloat16* Agh = (MODE == 0) ? g_hh : (MODE == 1) ? g_xrh : g_xsh;
    const __nv_bfloat16* Agl = (MODE == 0) ? g_hl : (MODE == 1) ? g_xrl : g_xsl;

    int tid = threadIdx.x, wid = tid >> 5, lane = tid & 31;
    int bm = blockIdx.y * 128, bn = blockIdx.x * 128;
    int wm = wid & 1, wn = wid >> 1;

    // cp.async addressing: 512 16B-granules per plane; 2 per thread
    int r0 = tid >> 2, c0 = (tid & 3) << 3;                 // granule 0: row, elem-offset
    int r1 = (tid + 256) >> 2, c1 = ((tid + 256) & 3) << 3; // granule 1
    uint32_t uAh = smem_u32(sAh), uAl = smem_u32(sAl);
    uint32_t uBh = smem_u32(sBh), uBl = smem_u32(sBl);
    uint32_t d0 = (uint32_t)(r0*APITCH + c0)*2, d1 = (uint32_t)(r1*APITCH + c1)*2;

    // ldmatrix per-lane byte offsets
    int lr = lane & 7, sel = lane >> 3;
    uint32_t a_off[4], b_off[2];
    #pragma unroll
    for (int mt = 0; mt < 4; mt++)
        a_off[mt] = (uint32_t)(((wm*64 + mt*16 + lr + ((sel & 1) << 3))*APITCH + ((sel >> 1) << 3)) * 2);
    #pragma unroll
    for (int ntp = 0; ntp < 2; ntp++)
        b_off[ntp] = (uint32_t)(((wn*32 + ntp*16 + lr + ((sel >> 1) << 3))*APITCH + ((sel & 1) << 3)) * 2);

    float acc[4][4][4];
    #pragma unroll
    for (int mt = 0; mt < 4; mt++)
        #pragma unroll
        for (int nt = 0; nt < 4; nt++)
            #pragma unroll
            for (int q = 0; q < 4; q++) acc[mt][nt][q] = 0.f;

    const int NC = K / 32;
    for (int c = 0; c < NC; c++) {
        int k0 = c * 32;
        __syncthreads();   // previous compute done
        cpa16(uAh + d0, Agh + (size_t)(bm + r0)*K + k0 + c0);
        cpa16(uAh + d1, Agh + (size_t)(bm + r1)*K + k0 + c1);
        cpa16(uAl + d0, Agl + (size_t)(bm + r0)*K + k0 + c0);
        cpa16(uAl + d1, Agl + (size_t)(bm + r1)*K + k0 + c1);
        cpa16(uBh + d0, Wh + (size_t)(bn + r0)*K + k0 + c0);
        cpa16(uBh + d1, Wh + (size_t)(bn + r1)*K + k0 + c1);
        cpa16(uBl + d0, Wl + (size_t)(bn + r0)*K + k0 + c0);
        cpa16(uBl + d1, Wl + (size_t)(bn + r1)*K + k0 + c1);
        cpa_wait();
        __syncthreads();

        #pragma unroll
        for (int ks = 0; ks < 32; ks += 16) {
            uint32_t bh[4][2], bl[4][2], af[4][4];
            #pragma unroll
            for (int ntp = 0; ntp < 2; ntp++) {
                uint32_t r[4];
                ldsm4(r, uBh + b_off[ntp] + ks*2);
                bh[2*ntp][0] = r[0]; bh[2*ntp][1] = r[1];
                bh[2*ntp+1][0] = r[2]; bh[2*ntp+1][1] = r[3];
            }
            #pragma unroll
            for (int ntp = 0; ntp < 2; ntp++) {
                uint32_t r[4];
                ldsm4(r, uBl + b_off[ntp] + ks*2);
                bl[2*ntp][0] = r[0]; bl[2*ntp][1] = r[1];
                bl[2*ntp+1][0] = r[2]; bl[2*ntp+1][1] = r[3];
            }
            #pragma unroll
            for (int mt = 0; mt < 4; mt++) ldsm4(af[mt], uAh + a_off[mt] + ks*2);
            #pragma unroll
            for (int mt = 0; mt < 4; mt++)
                #pragma unroll
                for (int nt = 0; nt < 4; nt++) mma16816(acc[mt][nt], af[mt], bh[nt]);
            #pragma unroll
            for (int mt = 0; mt < 4; mt++)
                #pragma unroll
                for (int nt = 0; nt < 4; nt++) mma16816(acc[mt][nt], af[mt], bl[nt]);
            #pragma unroll
            for (int mt = 0; mt < 4; mt++) ldsm4(af[mt], uAl + a_off[mt] + ks*2);
            #pragma unroll
            for (int mt = 0; mt < 4; mt++)
                #pragma unroll
                for (int nt = 0; nt < 4; nt++) mma16816(acc[mt][nt], af[mt], bh[nt]);
        }
    }

    // ---- epilogue ----
    int g = lane >> 2, tg = lane & 3;
    #pragma unroll
    for (int mt = 0; mt < 4; mt++) {
        #pragma unroll
        for (int nt = 0; nt < 4; nt++) {
            int gn = bn + wn*32 + nt*8 + 2*tg;
            #pragma unroll
            for (int half = 0; half < 2; half++) {
                int gm = bm + wm*64 + mt*16 + g + half*8;
                float v0 = acc[mt][nt][half*2 + 0];
                float v1 = acc[mt][nt][half*2 + 1];
                if (MODE == 0) {
                    v0 += bias[gn]; v1 += bias[gn + 1];
                    if (bn < DIi)
                        *(float2*)(g_xraw + (size_t)gm*DIi + gn) = make_float2(v0, v1);
                    else
                        *(float2*)(g_r + (size_t)gm*DIi + gn - DIi) = make_float2(v0, v1);
                } else if (MODE == 1) {
                    float2 h = *(const float2*)(g_h + (size_t)gm*DD + gn);
                    h.x += v0 + bias[gn];
                    h.y += v1 + bias[gn + 1];
                    *(float2*)(g_h + (size_t)gm*DD + gn) = h;
                    __nv_bfloat16 h0 = __float2bfloat16_rn(h.x);
                    __nv_bfloat16 h1 = __float2bfloat16_rn(h.y);
                    __nv_bfloat162 ph; ph.x = h0; ph.y = h1;
                    __nv_bfloat162 pl;
                    pl.x = __float2bfloat16_rn(h.x - __bfloat162float(h0));
                    pl.y = __float2bfloat16_rn(h.y - __bfloat162float(h1));
                    *(__nv_bfloat162*)(g_hh + (size_t)gm*DD + gn) = ph;
                    *(__nv_bfloat162*)(g_hl + (size_t)gm*DD + gn) = pl;
                } else {
                    if (gn < NXP)
                        *(float2*)(g_dbl + (size_t)gm*NXP + gn) = make_float2(v0, v1);
                }
            }
        }
    }
}

// ---------------- causal depthwise conv (k=4) + silu + bf16 split ----------------
__global__ void conv_silu_k(const float* __restrict__ cw, const float* __restrict__ cb) {
    int idx = blockIdx.x * blockDim.x + threadIdx.x;
    int d = idx & (DIi - 1);
    int t = idx >> 9;
    int l = t & (LL - 1);
    float acc = cb[d];
    #pragma unroll
    for (int j = 0; j < DCc; j++) {
        int lj = l + j - (DCc - 1);
        if (lj >= 0)
            acc += g_xraw[(size_t)(t + j - (DCc - 1))*DIi + d] * cw[d*DCc + j];
    }
    float s = acc / (1.f + __expf(-acc));
    g_xs[idx] = s;
    __nv_bfloat16 hh = __float2bfloat16_rn(s);
    g_xsh[idx] = hh;
    g_xsl[idx] = __float2bfloat16_rn(s - __bfloat162float(hh));
}

// ------- selective scan: delta=softplus(dt@dt_w+dt_b), D*u, silu(r) gate, bf16-split out -------
__global__ __launch_bounds__(128) void scan_k(const float* __restrict__ Alog,
                                              const float* __restrict__ Dp,
                                              const float* __restrict__ dtw,
                                              const float* __restrict__ dtb) {
    int b = blockIdx.x >> 2;
    int d = ((blockIdx.x & 3) << 7) + threadIdx.x;

    float Av[DSs];
    bool ia = true;
    #pragma unroll
    for (int s = 0; s < DSs; s++) {
        Av[s] = -__expf(Alog[d*DSs + s]);
        ia = ia && (fabsf(Av[s] + (float)(s+1)) < 1e-4f);
    }
    float wr[DTRr];
    #pragma unroll
    for (int r2 = 0; r2 < DTRr; r2++) wr[r2] = dtw[r2*DIi + d];
    float dtb_d = dtb[d];
    float Dd = Dp[d];

    float hs[DSs];
    #pragma unroll
    for (int s = 0; s < DSs; s++) hs[s] = 0.f;

    size_t tb = (size_t)b*LL;
    float u_n = g_xs[tb*DIi + d];
    float r_n = g_r [tb*DIi + d];

    for (int l = 0; l < LL; l++) {
        size_t t = tb + l;
        float u  = u_n;
        float rr = r_n;
        if (l + 1 < LL) {
            u_n = g_xs[(t+1)*DIi + d];
            r_n = g_r [(t+1)*DIi + d];
        }
        union { float4 v[12]; float f[48]; } q;
        const float4* qp = (const float4*)(g_dbl + t*NXP);
        #pragma unroll
        for (int i = 0; i < 12; i++) q.v[i] = qp[i];

        float xv = dtb_d;
        #pragma unroll
        for (int r2 = 0; r2 < DTRr; r2++) xv += q.f[r2]*wr[r2];
        float dlt = fmaxf(xv, 0.f) + __logf(1.f + __expf(-fabsf(xv)));
        float du = dlt*u;

        float e[DSs];
        if (ia) {
            float p = __expf(-dlt);
            e[0] = p;
            #pragma unroll
            for (int s = 1; s < DSs; s++) e[s] = e[s>>1]*e[(s-1)>>1];
        } else {
            #pragma unroll
            for (int s = 0; s < DSs; s++) e[s] = __expf(dlt*Av[s]);
        }

        float y = 0.f;
        #pragma unroll
        for (int s = 0; s < DSs; s++) {
            hs[s] = e[s]*hs[s] + du*q.f[16 + s];
            y += hs[s]*q.f[32 + s];
        }
        float sg = rr / (1.f + __expf(-rr));
        float yo = (y + u*Dd)*sg;
        __nv_bfloat16 hh = __float2bfloat16_rn(yo);
        g_xrh[t*DIi + d] = hh;
        g_xrl[t*DIi + d] = __float2bfloat16_rn(yo - __bfloat162float(hh));
    }
}

// ---------------- fused LayerNorm + mean-pool ----------------
__global__ __launch_bounds__(256) void lnpool_k(const float* __restrict__ g,
                                                const float* __restrict__ bln) {
    int b = blockIdx.x;
    int d = threadIdx.x;
    int wid = d >> 5, lane = d & 31;
    __shared__ float ws[8], wq[8];
    float acc = 0.f;
    for (int l = 0; l < LL; l++) {
        size_t t = (size_t)b*LL + l;
        float v = g_h[t*DD + d];
        float s = v, qq = v*v;
        #pragma unroll
        for (int o = 16; o > 0; o >>= 1) {
            s  += __shfl_down_sync(0xffffffffu, s, o);
            qq += __shfl_down_sync(0xffffffffu, qq, o);
        }
        if (lane == 0) { ws[wid] = s; wq[wid] = qq; }
        __syncthreads();
        float S = 0.f, Q = 0.f;
        #pragma unroll
        for (int i = 0; i < 8; i++) { S += ws[i]; Q += wq[i]; }
        float mu = S * (1.f/DD);
        float var = Q * (1.f/DD) - mu*mu;
        acc += (v - mu) * rsqrtf(var + 1e-5f);
        __syncthreads();
    }
    g_p[b*DD + d] = g[d]*acc*(1.f/LL) + bln[d];
}

// ---------------- MLP head ----------------
__global__ __launch_bounds__(128) void head_k(const float* __restrict__ w1,
                                              const float* __restrict__ b1,
                                              const float* __restrict__ w2,
                                              const float* __restrict__ b2,
                                              float* __restrict__ out) {
    int b = blockIdx.x;
    int j = threadIdx.x;
    float hsum = b1[j];
    #pragma unroll 8
    for (int d = 0; d < DD; d++) hsum += g_p[b*DD + d]*w1[d*DH + j];
    hsum = fmaxf(hsum, 0.f);
    __shared__ float s0[DH], s1[DH];
    s0[j] = hsum*w2[j*2];
    s1[j] = hsum*w2[j*2 + 1];
    __syncthreads();
    #pragma unroll
    for (int st = 64; st > 0; st >>= 1) {
        if (j < st) { s0[j] += s0[j + st]; s1[j] += s1[j + st]; }
        __syncthreads();
    }
    if (j == 0) {
        out[b*2]     = s0[0] + b2[0];
        out[b*2 + 1] = s1[0] + b2[1];
    }
}

// ---------------- launcher ----------------
extern "C" void kernel_launch(void* const* d_in, const int* in_sizes, int n_in,
                              void* d_out, int out_size) {
    const int*   x       = (const int*)  d_in[0];
    const float* emb     = (const float*)d_in[1];
    const float* in_w    = (const float*)d_in[2];
    const float* in_b    = (const float*)d_in[3];
    const float* conv_w  = (const float*)d_in[4];
    const float* conv_b  = (const float*)d_in[5];
    const float* xproj_w = (const float*)d_in[6];
    const float* dt_w    = (const float*)d_in[7];
    const float* dt_b    = (const float*)d_in[8];
    const float* A_log   = (const float*)d_in[9];
    const float* Dp      = (const float*)d_in[10];
    const float* out_w   = (const float*)d_in[11];
    const float* out_b   = (const float*)d_in[12];
    const float* ln_g    = (const float*)d_in[13];
    const float* ln_b    = (const float*)d_in[14];
    const float* w1      = (const float*)d_in[15];
    const float* b1      = (const float*)d_in[16];
    const float* w2      = (const float*)d_in[17];
    const float* b2      = (const float*)d_in[18];
    float* out = (float*)d_out;

    __nv_bfloat16 *wbh, *wbl;
    cudaGetSymbolAddress((void**)&wbh, g_wbh);
    cudaGetSymbolAddress((void**)&wbl, g_wbl);

    embed_k<<<(TT*DD)/256, 256>>>(x, emb);
    vt_k<<<64, 256>>>(emb, in_w, in_b);            // layer-0 in_proj table

    // weight transpose + bf16 split (K-major)
    for (int l = 0; l < NLl; l++) {
        size_t wo = (size_t)l*WT_LAY;
        if (l > 0)
            tsplit_k<<<(1024*256)/256, 256>>>(in_w + (size_t)l*DD*2*DIi,
                                              wbh + wo + WT_IN, wbl + wo + WT_IN, 1024, 8);
        tsplit_k<<<(128*512)/256, 256>>>(xproj_w + (size_t)l*DIi*NXP,
                                         wbh + wo + WT_XP, wbl + wo + WT_XP, NXP, 9);
        tsplit_k<<<(256*512)/256, 256>>>(out_w + (size_t)l*DIi*DD,
                                         wbh + wo + WT_OUT, wbl + wo + WT_OUT, DD, 9);
    }

    for (int l = 0; l < NLl; l++) {
        size_t wo = (size_t)l*WT_LAY;
        if (l == 0) {
            gather_k<<<(TT*128)/256, 256>>>(x);    // in_proj L0 = table lookup
        } else {
            mmagemm_k<0,256><<<dim3(8, TT/128), 256>>>(wbh + wo + WT_IN, wbl + wo + WT_IN,
                                                       in_b + (size_t)l*2*DIi);
        }
        conv_silu_k<<<(TT*DIi)/256, 256>>>(conv_w + (size_t)l*DIi*DCc, conv_b + (size_t)l*DIi);
        mmagemm_k<2,512><<<dim3(1, TT/128), 256>>>(wbh + wo + WT_XP, wbl + wo + WT_XP, nullptr);
        scan_k<<<BB*4, 128>>>(A_log + (size_t)l*DIi*DSs, Dp + (size_t)l*DIi,
                              dt_w + (size_t)l*DTRr*DIi, dt_b + (size_t)l*DIi);
        mmagemm_k<1,512><<<dim3(2, TT/128), 256>>>(wbh + wo + WT_OUT, wbl + wo + WT_OUT,
                                                   out_b + (size_t)l*DD);
    }

    lnpool_k<<<BB, 256>>>(ln_g, ln_b);
    head_k<<<BB, DH>>>(w1, b1, w2, b2, out);
}

// round 12
// speedup vs baseline: 1.9825x; 1.0309x over previous
#include <cuda_runtime.h>
#include <cuda_bf16.h>
#include <math.h>
#include <stdint.h>

// Problem constants
#define BB   256
#define LL   512
#define TT   (BB*LL)     // 131072 tokens
#define DD   256
#define DIi  512
#define DSs  16
#define DCc  4
#define DTRr 16
#define NLl  2
#define NXP  48
#define DH   128
#define APITCH 40        // smem row pitch in bf16 elems (80B): conflict-free ldmatrix

// ---------------- scratch (static, no allocation) ----------------
__device__ float g_h[(size_t)TT*DD];        // residual stream fp32
__device__ float g_xraw[(size_t)TT*DIi];    // in_proj xs output (conv input)
__device__ float g_r[(size_t)TT*DIi];       // gate r
__device__ float g_dbl[(size_t)TT*NXP];     // dt|B|C
__device__ float g_p[BB*DD];
__device__ float g_vt[64*1024];             // vocab table for layer-0 in_proj
// bf16 hi/lo activation planes (GEMM A operands)
__device__ __nv_bfloat16 g_hh[(size_t)TT*DD],  g_hl[(size_t)TT*DD];    // h split (in_proj L1)
__device__ __nv_bfloat16 g_xrh[(size_t)TT*DIi], g_xrl[(size_t)TT*DIi]; // scan y split (out_proj)
__device__ __nv_bfloat16 g_xsh[(size_t)TT*DIi], g_xsl[(size_t)TT*DIi]; // xs split (x_proj + scan u)
// bf16 hi/lo weights, K-major [Npad][K]: in[1024][256] | xp[128][512] | out[256][512]
#define WT_IN   0
#define WT_XP   262144
#define WT_OUT  327680
#define WT_LAY  458752
__device__ __nv_bfloat16 g_wbh[2*WT_LAY], g_wbl[2*WT_LAY];

// ---------------- PTX helpers (arch-agnostic: sm_80-era only) ----------------
__device__ __forceinline__ uint32_t smem_u32(const void* p) {
    uint32_t a;
    asm("{ .reg .u64 t; cvta.to.shared.u64 t, %1; cvt.u32.u64 %0, t; }" : "=r"(a) : "l"(p));
    return a;
}
__device__ __forceinline__ void cpa16(uint32_t dst, const void* src) {
    asm volatile("cp.async.cg.shared.global [%0], [%1], 16;" :: "r"(dst), "l"(src));
}
__device__ __forceinline__ void ldsm4(uint32_t* r, uint32_t addr) {
    asm volatile("ldmatrix.sync.aligned.m8n8.x4.shared.b16 {%0,%1,%2,%3}, [%4];"
        : "=r"(r[0]), "=r"(r[1]), "=r"(r[2]), "=r"(r[3]) : "r"(addr));
}
__device__ __forceinline__ void mma16816(float* d, const uint32_t* a, const uint32_t* b) {
    asm volatile(
        "mma.sync.aligned.m16n8k16.row.col.f32.bf16.bf16.f32 "
        "{%0,%1,%2,%3}, {%4,%5,%6,%7}, {%8,%9}, {%0,%1,%2,%3};"
        : "+f"(d[0]), "+f"(d[1]), "+f"(d[2]), "+f"(d[3])
        : "r"(a[0]), "r"(a[1]), "r"(a[2]), "r"(a[3]), "r"(b[0]), "r"(b[1]));
}

// ---------------- embedding ----------------
__global__ void embed_k(const int* __restrict__ x, const float* __restrict__ emb) {
    int idx = blockIdx.x * blockDim.x + threadIdx.x;
    int t = idx >> 8, d = idx & 255;
    g_h[idx] = emb[x[t]*DD + d];
}

// ---------------- vocab table: VT = emb @ in_w0 + in_b0 ----------------
__global__ __launch_bounds__(256) void vt_k(const float* __restrict__ emb,
                                            const float* __restrict__ w,
                                            const float* __restrict__ b) {
    __shared__ float se[DD];
    int v = blockIdx.x;
    for (int i = threadIdx.x; i < DD; i += 256) se[i] = emb[v*DD + i];
    __syncthreads();
    #pragma unroll
    for (int jj = 0; jj < 4; jj++) {
        int col = threadIdx.x + jj*256;
        float acc = b[col];
        for (int k = 0; k < DD; k++) acc += se[k]*w[(size_t)k*1024 + col];
        g_vt[v*1024 + col] = acc;
    }
}

// ---------------- layer-0 in_proj = gather from VT ----------------
__global__ void gather_k(const int* __restrict__ x) {
    int idx = blockIdx.x * blockDim.x + threadIdx.x;   // TT*128
    int t = idx >> 7, q = (idx & 127) << 2;
    int v = x[t];
    float4 a = *(const float4*)(g_vt + v*1024 + q);
    float4 bb = *(const float4*)(g_vt + v*1024 + 512 + q);
    *(float4*)(g_xraw + (size_t)t*DIi + q) = a;
    *(float4*)(g_r    + (size_t)t*DIi + q) = bb;
}

// ---------------- weight transpose + bf16 hi/lo split ----------------
__global__ void tsplit_k(const float* __restrict__ src, __nv_bfloat16* __restrict__ dh,
                         __nv_bfloat16* __restrict__ dl, int N, int kshift) {
    int idx = blockIdx.x * blockDim.x + threadIdx.x;
    int K = 1 << kshift;
    int k = idx & (K - 1), n = idx >> kshift;
    float v = (n < N) ? src[(size_t)k*N + n] : 0.f;
    __nv_bfloat16 h = __float2bfloat16_rn(v);
    dh[idx] = h;
    dl[idx] = __float2bfloat16_rn(v - __bfloat162float(h));
}

// ---------------- bf16-split mma.sync GEMM, 2-stage cp.async pipeline ----------------
// MODE 0: A = g_hh/g_hl   -> g_xraw | g_r (+bias)      (in_proj L1, K=256, BN=128)
// MODE 1: A = g_xrh/g_xrl -> g_h += (+bias), + h split (out_proj,  K=512, BN=128)
// MODE 2: A = g_xsh/g_xsl -> g_dbl cols<48             (x_proj,    K=512, BN=64)
template<int MODE, int K, int BN>
__global__ void __launch_bounds__(256, 2) mmagemm_k(const __nv_bfloat16* __restrict__ Wh,
                                                    const __nv_bfloat16* __restrict__ Wl,
                                                    const float* __restrict__ bias) {
    extern __shared__ char smem[];
    constexpr int ABYTES = 128*APITCH*2;
    constexpr int BBYTES = BN*APITCH*2;
    constexpr int STAGE  = 2*ABYTES + 2*BBYTES;
    constexpr int MT = (BN == 128) ? 4 : 2;     // 16-row subtiles per warp

    const __nv_bfloat16* Agh = (MODE == 0) ? g_hh : (MODE == 1) ? g_xrh : g_xsh;
    const __nv_bfloat16* Agl = (MODE == 0) ? g_hl : (MODE == 1) ? g_xrl : g_xsl;

    int tid = threadIdx.x, wid = tid >> 5, lane = tid & 31;
    int bm = blockIdx.y * 128, bn = blockIdx.x * BN;
    int wm = (BN == 128) ? (wid & 1)  : (wid & 3);
    int wn = (BN == 128) ? (wid >> 1) : (wid >> 2);

    uint32_t base = smem_u32(smem);

    // per-thread cp.async addressing (16B granules of a 128x32 bf16 chunk)
    int r0 = tid >> 2,         c0 = (tid & 3) << 3;
    int r1 = (tid + 256) >> 2, c1 = ((tid + 256) & 3) << 3;
    uint32_t dA0 = (uint32_t)(r0*APITCH + c0)*2, dA1 = (uint32_t)(r1*APITCH + c1)*2;

    // ldmatrix per-lane byte offsets (relative to plane base)
    int lr = lane & 7, sel = lane >> 3;
    uint32_t a_off[4], b_off[2];
    #pragma unroll
    for (int mt = 0; mt < MT; mt++)
        a_off[mt] = (uint32_t)(((wm*(MT*16) + mt*16 + lr + ((sel & 1) << 3))*APITCH + ((sel >> 1) << 3)) * 2);
    #pragma unroll
    for (int ntp = 0; ntp < 2; ntp++)
        b_off[ntp] = (uint32_t)(((wn*32 + ntp*16 + lr + ((sel >> 1) << 3))*APITCH + ((sel & 1) << 3)) * 2);

    float acc[MT][4][4];
    #pragma unroll
    for (int mt = 0; mt < MT; mt++)
        #pragma unroll
        for (int nt = 0; nt < 4; nt++)
            #pragma unroll
            for (int q = 0; q < 4; q++) acc[mt][nt][q] = 0.f;

    const int NC = K / 32;

    auto issue = [&](int c) {
        uint32_t sb = base + (uint32_t)(c & 1)*STAGE;
        int k0 = c * 32;
        cpa16(sb + dA0,          Agh + (size_t)(bm + r0)*K + k0 + c0);
        cpa16(sb + dA1,          Agh + (size_t)(bm + r1)*K + k0 + c1);
        cpa16(sb + ABYTES + dA0, Agl + (size_t)(bm + r0)*K + k0 + c0);
        cpa16(sb + ABYTES + dA1, Agl + (size_t)(bm + r1)*K + k0 + c1);
        if (BN == 128) {
            cpa16(sb + 2*ABYTES + dA0,          Wh + (size_t)(bn + r0)*K + k0 + c0);
            cpa16(sb + 2*ABYTES + dA1,          Wh + (size_t)(bn + r1)*K + k0 + c1);
            cpa16(sb + 2*ABYTES + BBYTES + dA0, Wl + (size_t)(bn + r0)*K + k0 + c0);
            cpa16(sb + 2*ABYTES + BBYTES + dA1, Wl + (size_t)(bn + r1)*K + k0 + c1);
        } else {
            cpa16(sb + 2*ABYTES + dA0,          Wh + (size_t)(bn + r0)*K + k0 + c0);
            cpa16(sb + 2*ABYTES + BBYTES + dA0, Wl + (size_t)(bn + r0)*K + k0 + c0);
        }
        asm volatile("cp.async.commit_group;" ::: "memory");
    };

    issue(0);
    for (int c = 0; c < NC; c++) {
        if (c + 1 < NC) {
            issue(c + 1);
            asm volatile("cp.async.wait_group 1;" ::: "memory");
        } else {
            asm volatile("cp.async.wait_group 0;" ::: "memory");
        }
        __syncthreads();

        uint32_t sb  = base + (uint32_t)(c & 1)*STAGE;
        uint32_t uAh = sb, uAl = sb + ABYTES;
        uint32_t uBh = sb + 2*ABYTES, uBl = sb + 2*ABYTES + BBYTES;

        #pragma unroll
        for (int ks = 0; ks < 32; ks += 16) {
            uint32_t bh[4][2], bl[4][2], af[4][4];
            #pragma unroll
            for (int ntp = 0; ntp < 2; ntp++) {
                uint32_t r[4];
                ldsm4(r, uBh + b_off[ntp] + ks*2);
                bh[2*ntp][0] = r[0]; bh[2*ntp][1] = r[1];
                bh[2*ntp+1][0] = r[2]; bh[2*ntp+1][1] = r[3];
            }
            #pragma unroll
            for (int ntp = 0; ntp < 2; ntp++) {
                uint32_t r[4];
                ldsm4(r, uBl + b_off[ntp] + ks*2);
                bl[2*ntp][0] = r[0]; bl[2*ntp][1] = r[1];
                bl[2*ntp+1][0] = r[2]; bl[2*ntp+1][1] = r[3];
            }
            #pragma unroll
            for (int mt = 0; mt < MT; mt++) ldsm4(af[mt], uAh + a_off[mt] + ks*2);
            #pragma unroll
            for (int mt = 0; mt < MT; mt++)
                #pragma unroll
                for (int nt = 0; nt < 4; nt++) mma16816(acc[mt][nt], af[mt], bh[nt]);
            #pragma unroll
            for (int mt = 0; mt < MT; mt++)
                #pragma unroll
                for (int nt = 0; nt < 4; nt++) mma16816(acc[mt][nt], af[mt], bl[nt]);
            #pragma unroll
            for (int mt = 0; mt < MT; mt++) ldsm4(af[mt], uAl + a_off[mt] + ks*2);
            #pragma unroll
            for (int mt = 0; mt < MT; mt++)
                #pragma unroll
                for (int nt = 0; nt < 4; nt++) mma16816(acc[mt][nt], af[mt], bh[nt]);
        }
        __syncthreads();
    }

    // ---- epilogue ----
    int g = lane >> 2, tg = lane & 3;
    #pragma unroll
    for (int mt = 0; mt < MT; mt++) {
        #pragma unroll
        for (int nt = 0; nt < 4; nt++) {
            int gn = bn + wn*32 + nt*8 + 2*tg;
            #pragma unroll
            for (int half = 0; half < 2; half++) {
                int gm = bm + wm*(MT*16) + mt*16 + g + half*8;
                float v0 = acc[mt][nt][half*2 + 0];
                float v1 = acc[mt][nt][half*2 + 1];
                if (MODE == 0) {
                    v0 += bias[gn]; v1 += bias[gn + 1];
                    if (bn < DIi)
                        *(float2*)(g_xraw + (size_t)gm*DIi + gn) = make_float2(v0, v1);
                    else
                        *(float2*)(g_r + (size_t)gm*DIi + gn - DIi) = make_float2(v0, v1);
                } else if (MODE == 1) {
                    float2 h = *(const float2*)(g_h + (size_t)gm*DD + gn);
                    h.x += v0 + bias[gn];
                    h.y += v1 + bias[gn + 1];
                    *(float2*)(g_h + (size_t)gm*DD + gn) = h;
                    __nv_bfloat16 h0 = __float2bfloat16_rn(h.x);
                    __nv_bfloat16 h1 = __float2bfloat16_rn(h.y);
                    __nv_bfloat162 ph; ph.x = h0; ph.y = h1;
                    __nv_bfloat162 pl;
                    pl.x = __float2bfloat16_rn(h.x - __bfloat162float(h0));
                    pl.y = __float2bfloat16_rn(h.y - __bfloat162float(h1));
                    *(__nv_bfloat162*)(g_hh + (size_t)gm*DD + gn) = ph;
                    *(__nv_bfloat162*)(g_hl + (size_t)gm*DD + gn) = pl;
                } else {
                    if (gn < NXP)
                        *(float2*)(g_dbl + (size_t)gm*NXP + gn) = make_float2(v0, v1);
                }
            }
        }
    }
}

// ---------------- causal depthwise conv (k=4) + silu -> bf16 split only ----------------
__global__ void conv_silu_k(const float* __restrict__ cw, const float* __restrict__ cb) {
    int idx = blockIdx.x * blockDim.x + threadIdx.x;
    int d = idx & (DIi - 1);
    int t = idx >> 9;
    int l = t & (LL - 1);
    float acc = cb[d];
    #pragma unroll
    for (int j = 0; j < DCc; j++) {
        int lj = l + j - (DCc - 1);
        if (lj >= 0)
            acc += g_xraw[(size_t)(t + j - (DCc - 1))*DIi + d] * cw[d*DCc + j];
    }
    float s = acc / (1.f + __expf(-acc));
    __nv_bfloat16 hh = __float2bfloat16_rn(s);
    g_xsh[idx] = hh;
    g_xsl[idx] = __float2bfloat16_rn(s - __bfloat162float(hh));
}

// ------- selective scan: delta=softplus(dt@dt_w+dt_b), D*u, silu(r) gate, bf16-split out -------
__global__ __launch_bounds__(128) void scan_k(const float* __restrict__ Alog,
                                              const float* __restrict__ Dp,
                                              const float* __restrict__ dtw,
                                              const float* __restrict__ dtb) {
    int b = blockIdx.x >> 2;
    int d = ((blockIdx.x & 3) << 7) + threadIdx.x;

    float Av[DSs];
    bool ia = true;
    #pragma unroll
    for (int s = 0; s < DSs; s++) {
        Av[s] = -__expf(Alog[d*DSs + s]);
        ia = ia && (fabsf(Av[s] + (float)(s+1)) < 1e-4f);
    }
    float wr[DTRr];
    #pragma unroll
    for (int r2 = 0; r2 < DTRr; r2++) wr[r2] = dtw[r2*DIi + d];
    float dtb_d = dtb[d];
    float Dd = Dp[d];

    float hs[DSs];
    #pragma unroll
    for (int s = 0; s < DSs; s++) hs[s] = 0.f;

    size_t tb = (size_t)b*LL;
    float u_n = __bfloat162float(g_xsh[tb*DIi + d]) + __bfloat162float(g_xsl[tb*DIi + d]);
    float r_n = g_r[tb*DIi + d];

    for (int l = 0; l < LL; l++) {
        size_t t = tb + l;
        float u  = u_n;
        float rr = r_n;
        if (l + 1 < LL) {
            u_n = __bfloat162float(g_xsh[(t+1)*DIi + d]) + __bfloat162float(g_xsl[(t+1)*DIi + d]);
            r_n = g_r[(t+1)*DIi + d];
        }
        union { float4 v[12]; float f[48]; } q;
        const float4* qp = (const float4*)(g_dbl + t*NXP);
        #pragma unroll
        for (int i = 0; i < 12; i++) q.v[i] = qp[i];

        float xv = dtb_d;
        #pragma unroll
        for (int r2 = 0; r2 < DTRr; r2++) xv += q.f[r2]*wr[r2];
        float dlt = fmaxf(xv, 0.f) + __logf(1.f + __expf(-fabsf(xv)));
        float du = dlt*u;

        float e[DSs];
        if (ia) {
            float p = __expf(-dlt);
            e[0] = p;
            #pragma unroll
            for (int s = 1; s < DSs; s++) e[s] = e[s>>1]*e[(s-1)>>1];
        } else {
            #pragma unroll
            for (int s = 0; s < DSs; s++) e[s] = __expf(dlt*Av[s]);
        }

        float y = 0.f;
        #pragma unroll
        for (int s = 0; s < DSs; s++) {
            hs[s] = e[s]*hs[s] + du*q.f[16 + s];
            y += hs[s]*q.f[32 + s];
        }
        float sg = rr / (1.f + __expf(-rr));
        float yo = (y + u*Dd)*sg;
        __nv_bfloat16 hh = __float2bfloat16_rn(yo);
        g_xrh[t*DIi + d] = hh;
        g_xrl[t*DIi + d] = __float2bfloat16_rn(yo - __bfloat162float(hh));
    }
}

// ---------------- fused LayerNorm + mean-pool ----------------
__global__ __launch_bounds__(256) void lnpool_k(const float* __restrict__ g,
                                                const float* __restrict__ bln) {
    int b = blockIdx.x;
    int d = threadIdx.x;
    int wid = d >> 5, lane = d & 31;
    __shared__ float ws[8], wq[8];
    float acc = 0.f;
    for (int l = 0; l < LL; l++) {
        size_t t = (size_t)b*LL + l;
        float v = g_h[t*DD + d];
        float s = v, qq = v*v;
        #pragma unroll
        for (int o = 16; o > 0; o >>= 1) {
            s  += __shfl_down_sync(0xffffffffu, s, o);
            qq += __shfl_down_sync(0xffffffffu, qq, o);
        }
        if (lane == 0) { ws[wid] = s; wq[wid] = qq; }
        __syncthreads();
        float S = 0.f, Q = 0.f;
        #pragma unroll
        for (int i = 0; i < 8; i++) { S += ws[i]; Q += wq[i]; }
        float mu = S * (1.f/DD);
        float var = Q * (1.f/DD) - mu*mu;
        acc += (v - mu) * rsqrtf(var + 1e-5f);
        __syncthreads();
    }
    g_p[b*DD + d] = g[d]*acc*(1.f/LL) + bln[d];
}

// ---------------- MLP head ----------------
__global__ __launch_bounds__(128) void head_k(const float* __restrict__ w1,
                                              const float* __restrict__ b1,
                                              const float* __restrict__ w2,
                                              const float* __restrict__ b2,
                                              float* __restrict__ out) {
    int b = blockIdx.x;
    int j = threadIdx.x;
    float hsum = b1[j];
    #pragma unroll 8
    for (int d = 0; d < DD; d++) hsum += g_p[b*DD + d]*w1[d*DH + j];
    hsum = fmaxf(hsum, 0.f);
    __shared__ float s0[DH], s1[DH];
    s0[j] = hsum*w2[j*2];
    s1[j] = hsum*w2[j*2 + 1];
    __syncthreads();
    #pragma unroll
    for (int st = 64; st > 0; st >>= 1) {
        if (j < st) { s0[j] += s0[j + st]; s1[j] += s1[j + st]; }
        __syncthreads();
    }
    if (j == 0) {
        out[b*2]     = s0[0] + b2[0];
        out[b*2 + 1] = s1[0] + b2[1];
    }
}

// ---------------- launcher ----------------
extern "C" void kernel_launch(void* const* d_in, const int* in_sizes, int n_in,
                              void* d_out, int out_size) {
    const int*   x       = (const int*)  d_in[0];
    const float* emb     = (const float*)d_in[1];
    const float* in_w    = (const float*)d_in[2];
    const float* in_b    = (const float*)d_in[3];
    const float* conv_w  = (const float*)d_in[4];
    const float* conv_b  = (const float*)d_in[5];
    const float* xproj_w = (const float*)d_in[6];
    const float* dt_w    = (const float*)d_in[7];
    const float* dt_b    = (const float*)d_in[8];
    const float* A_log   = (const float*)d_in[9];
    const float* Dp      = (const float*)d_in[10];
    const float* out_w   = (const float*)d_in[11];
    const float* out_b   = (const float*)d_in[12];
    const float* ln_g    = (const float*)d_in[13];
    const float* ln_b    = (const float*)d_in[14];
    const float* w1      = (const float*)d_in[15];
    const float* b1      = (const float*)d_in[16];
    const float* w2      = (const float*)d_in[17];
    const float* b2      = (const float*)d_in[18];
    float* out = (float*)d_out;

    // dynamic smem opt-in (state change, not a stream op; safe under capture)
    const int SM128 = 2 * (2*128*APITCH*2 + 2*128*APITCH*2);  // 81920
    const int SM64  = 2 * (2*128*APITCH*2 + 2*64*APITCH*2);   // 61440
    cudaFuncSetAttribute(mmagemm_k<0,256,128>, cudaFuncAttributeMaxDynamicSharedMemorySize, SM128);
    cudaFuncSetAttribute(mmagemm_k<1,512,128>, cudaFuncAttributeMaxDynamicSharedMemorySize, SM128);
    cudaFuncSetAttribute(mmagemm_k<2,512,64>,  cudaFuncAttributeMaxDynamicSharedMemorySize, SM64);

    __nv_bfloat16 *wbh, *wbl;
    cudaGetSymbolAddress((void**)&wbh, g_wbh);
    cudaGetSymbolAddress((void**)&wbl, g_wbl);

    embed_k<<<(TT*DD)/256, 256>>>(x, emb);
    vt_k<<<64, 256>>>(emb, in_w, in_b);            // layer-0 in_proj table

    // weight transpose + bf16 split (K-major)
    for (int l = 0; l < NLl; l++) {
        size_t wo = (size_t)l*WT_LAY;
        if (l > 0)
            tsplit_k<<<(1024*256)/256, 256>>>(in_w + (size_t)l*DD*2*DIi,
                                              wbh + wo + WT_IN, wbl + wo + WT_IN, 1024, 8);
        tsplit_k<<<(128*512)/256, 256>>>(xproj_w + (size_t)l*DIi*NXP,
                                         wbh + wo + WT_XP, wbl + wo + WT_XP, NXP, 9);
        tsplit_k<<<(256*512)/256, 256>>>(out_w + (size_t)l*DIi*DD,
                                         wbh + wo + WT_OUT, wbl + wo + WT_OUT, DD, 9);
    }

    for (int l = 0; l < NLl; l++) {
        size_t wo = (size_t)l*WT_LAY;
        if (l == 0) {
            gather_k<<<(TT*128)/256, 256>>>(x);    // in_proj L0 = table lookup
        } else {
            mmagemm_k<0,256,128><<<dim3(8, TT/128), 256, SM128>>>(
                wbh + wo + WT_IN, wbl + wo + WT_IN, in_b + (size_t)l*2*DIi);
        }
        conv_silu_k<<<(TT*DIi)/256, 256>>>(conv_w + (size_t)l*DIi*DCc, conv_b + (size_t)l*DIi);
        mmagemm_k<2,512,64><<<dim3(1, TT/128), 256, SM64>>>(
            wbh + wo + WT_XP, wbl + wo + WT_XP, nullptr);
        scan_k<<<BB*4, 128>>>(A_log + (size_t)l*DIi*DSs, Dp + (size_t)l*DIi,
                              dt_w + (size_t)l*DTRr*DIi, dt_b + (size_t)l*DIi);
        mmagemm_k<1,512,128><<<dim3(2, TT/128), 256, SM128>>>(
            wbh + wo + WT_OUT, wbl + wo + WT_OUT, out_b + (size_t)l*DD);
    }

    lnpool_k<<<BB, 256>>>(ln_g, ln_b);
    head_k<<<BB, DH>>>(w1, b1, w2, b2, out);
}

// round 16
// speedup vs baseline: 2.3051x; 1.1627x over previous
#include <cuda_runtime.h>
#include <cuda_bf16.h>
#include <math.h>
#include <stdint.h>

// Problem constants
#define BB   256
#define LL   512
#define TT   (BB*LL)     // 131072 tokens
#define DD   256
#define DIi  512
#define DSs  16
#define DCc  4
#define DTRr 16
#define NLl  2
#define NXP  48
#define DH   128
#define APITCH 40        // smem row pitch in bf16 elems (80B): conflict-free ldmatrix

// ---------------- scratch (static, no allocation) ----------------
__device__ float g_h[(size_t)TT*DD];        // residual stream fp32
__device__ float g_xraw[(size_t)TT*DIi];    // layer-1 in_proj xs output (pre-conv)
__device__ float g_r[(size_t)TT*DIi];       // layer-1 gate r
__device__ float g_dbl[(size_t)TT*NXP];     // dt|B|C
__device__ float g_p[BB*DD];
__device__ float g_vt[64*1024];             // vocab table: emb @ in_w0 + in_b0
// bf16 hi/lo activation planes (GEMM A operands)
__device__ __nv_bfloat16 g_hh[(size_t)TT*DD],  g_hl[(size_t)TT*DD];    // h split (in_proj L1)
__device__ __nv_bfloat16 g_xrh[(size_t)TT*DIi], g_xrl[(size_t)TT*DIi]; // scan y split (out_proj)
// bf16 hi/lo weights, K-major [Npad][K]: in[1024][256] | xp[128][512] | out[256][512]
#define WT_IN   0
#define WT_XP   262144
#define WT_OUT  327680
#define WT_LAY  458752
__device__ __nv_bfloat16 g_wbh[2*WT_LAY], g_wbl[2*WT_LAY];

// ---------------- PTX helpers ----------------
__device__ __forceinline__ uint32_t smem_u32(const void* p) {
    uint32_t a;
    asm("{ .reg .u64 t; cvta.to.shared.u64 t, %1; cvt.u32.u64 %0, t; }" : "=r"(a) : "l"(p));
    return a;
}
__device__ __forceinline__ void cpa16(uint32_t dst, const void* src) {
    asm volatile("cp.async.cg.shared.global [%0], [%1], 16;" :: "r"(dst), "l"(src));
}
__device__ __forceinline__ void ldsm4(uint32_t* r, uint32_t addr) {
    asm volatile("ldmatrix.sync.aligned.m8n8.x4.shared.b16 {%0,%1,%2,%3}, [%4];"
        : "=r"(r[0]), "=r"(r[1]), "=r"(r[2]), "=r"(r[3]) : "r"(addr));
}
__device__ __forceinline__ void mma16816(float* d, const uint32_t* a, const uint32_t* b) {
    asm volatile(
        "mma.sync.aligned.m16n8k16.row.col.f32.bf16.bf16.f32 "
        "{%0,%1,%2,%3}, {%4,%5,%6,%7}, {%8,%9}, {%0,%1,%2,%3};"
        : "+f"(d[0]), "+f"(d[1]), "+f"(d[2]), "+f"(d[3])
        : "r"(a[0]), "r"(a[1]), "r"(a[2]), "r"(a[3]), "r"(b[0]), "r"(b[1]));
}

// ---------------- embedding ----------------
__global__ void embed_k(const int* __restrict__ x, const float* __restrict__ emb) {
    int idx = blockIdx.x * blockDim.x + threadIdx.x;
    int t = idx >> 8, d = idx & 255;
    g_h[idx] = emb[x[t]*DD + d];
}

// ---------------- vocab table: VT = emb @ in_w0 + in_b0 ----------------
__global__ __launch_bounds__(256) void vt_k(const float* __restrict__ emb,
                                            const float* __restrict__ w,
                                            const float* __restrict__ b) {
    __shared__ float se[DD];
    int v = blockIdx.x;
    for (int i = threadIdx.x; i < DD; i += 256) se[i] = emb[v*DD + i];
    __syncthreads();
    #pragma unroll
    for (int jj = 0; jj < 4; jj++) {
        int col = threadIdx.x + jj*256;
        float acc = b[col];
        for (int k = 0; k < DD; k++) acc += se[k]*w[(size_t)k*1024 + col];
        g_vt[v*1024 + col] = acc;
    }
}

// ---------------- weight transpose + bf16 hi/lo split ----------------
__global__ void tsplit_k(const float* __restrict__ src, __nv_bfloat16* __restrict__ dh,
                         __nv_bfloat16* __restrict__ dl, int N, int kshift) {
    int idx = blockIdx.x * blockDim.x + threadIdx.x;
    int K = 1 << kshift;
    int k = idx & (K - 1), n = idx >> kshift;
    float v = (n < N) ? src[(size_t)k*N + n] : 0.f;
    __nv_bfloat16 h = __float2bfloat16_rn(v);
    dh[idx] = h;
    dl[idx] = __float2bfloat16_rn(v - __bfloat162float(h));
}

// ============ fused conv+silu+x_proj GEMM (BN=64, N=48) ============
// IS_L0: raw = vt[x[token]][ch] gathered from L2-resident table
// else : raw = g_xraw stream
template<int IS_L0>
__global__ __launch_bounds__(256) void xproj_k(
    const __nv_bfloat16* __restrict__ Wh, const __nv_bfloat16* __restrict__ Wl,
    const float* __restrict__ cw, const float* __restrict__ cb,
    const int* __restrict__ x)
{
    __shared__ __align__(16) float sraw[131][33];
    __shared__ __align__(16) __nv_bfloat16 sAh[128*APITCH];
    __shared__ __align__(16) __nv_bfloat16 sAl[128*APITCH];
    __shared__ __align__(16) __nv_bfloat16 sBh[64*APITCH];
    __shared__ __align__(16) __nv_bfloat16 sBl[64*APITCH];
    __shared__ __align__(16) int sidx[132];

    int tid = threadIdx.x, wid = tid >> 5, lane = tid & 31;
    int bm = blockIdx.x * 128;
    int l0 = bm & (LL - 1);

    if (IS_L0 && tid < 131) {
        bool valid = (l0 > 0) || (tid >= 3);
        sidx[tid] = valid ? x[bm - 3 + tid] : -1;
    }

    int wm = wid & 3, wn = wid >> 2;        // 4 m-slices x 2 n-slices
    int lr = lane & 7, sel = lane >> 3;
    uint32_t uAh = smem_u32(sAh), uAl = smem_u32(sAl);
    uint32_t uBh = smem_u32(sBh), uBl = smem_u32(sBl);
    uint32_t a_off[2], b_off[2];
    #pragma unroll
    for (int mt = 0; mt < 2; mt++)
        a_off[mt] = (uint32_t)(((wm*32 + mt*16 + lr + ((sel & 1) << 3))*APITCH + ((sel >> 1) << 3)) * 2);
    #pragma unroll
    for (int ntp = 0; ntp < 2; ntp++)
        b_off[ntp] = (uint32_t)(((wn*32 + ntp*16 + lr + ((sel >> 1) << 3))*APITCH + ((sel & 1) << 3)) * 2);

    int ch = tid & 31, r0 = tid >> 5;       // conv mapping
    int brow = tid >> 2, bc8 = (tid & 3) << 3;  // B-load mapping

    float acc[2][4][4];
    #pragma unroll
    for (int mt = 0; mt < 2; mt++)
        #pragma unroll
        for (int nt = 0; nt < 4; nt++)
            #pragma unroll
            for (int q = 0; q < 4; q++) acc[mt][nt][q] = 0.f;

    if (IS_L0) __syncthreads();   // sidx ready

    for (int c = 0; c < 16; c++) {          // K = 512, 32-wide chunks
        __syncthreads();                    // previous chunk's smem reads done
        int k0 = c * 32;
        // raw tile: 131 rows x 32 ch
        #pragma unroll
        for (int i = 0; i < 17; i++) {
            int idx = tid + i*256;
            if (idx < 131*32) {
                int row = idx >> 5, col = idx & 31;
                float v;
                if (IS_L0) {
                    int vv = sidx[row];
                    v = (vv < 0) ? 0.f : g_vt[vv*1024 + k0 + col];
                } else {
                    bool valid = (l0 > 0) || (row >= 3);
                    v = valid ? g_xraw[(size_t)(bm - 3 + row)*DIi + k0 + col] : 0.f;
                }
                sraw[row][col] = v;
            }
        }
        // B chunk [64 rows x 32 k] hi/lo
        {
            uint4 vh = *(const uint4*)(Wh + (size_t)brow*512 + k0 + bc8);
            uint4 vl = *(const uint4*)(Wl + (size_t)brow*512 + k0 + bc8);
            *(uint4*)&sBh[brow*APITCH + bc8] = vh;
            *(uint4*)&sBl[brow*APITCH + bc8] = vl;
        }
        __syncthreads();

        // conv + silu + bf16 split -> A planes
        float w0 = cw[(k0 + ch)*4 + 0], w1 = cw[(k0 + ch)*4 + 1];
        float w2 = cw[(k0 + ch)*4 + 2], w3 = cw[(k0 + ch)*4 + 3];
        float bv = cb[k0 + ch];
        #pragma unroll
        for (int k = 0; k < 16; k++) {
            int l = r0 + k*8;
            float a = bv + sraw[l][ch]*w0 + sraw[l+1][ch]*w1
                        + sraw[l+2][ch]*w2 + sraw[l+3][ch]*w3;
            float s = a / (1.f + __expf(-a));
            __nv_bfloat16 hh = __float2bfloat16_rn(s);
            sAh[l*APITCH + ch] = hh;
            sAl[l*APITCH + ch] = __float2bfloat16_rn(s - __bfloat162float(hh));
        }
        __syncthreads();

        // MMA (3-product compensation)
        #pragma unroll
        for (int ks = 0; ks < 32; ks += 16) {
            uint32_t bh[4][2], bl[4][2], af[2][4];
            #pragma unroll
            for (int ntp = 0; ntp < 2; ntp++) {
                uint32_t r[4];
                ldsm4(r, uBh + b_off[ntp] + ks*2);
                bh[2*ntp][0] = r[0]; bh[2*ntp][1] = r[1];
                bh[2*ntp+1][0] = r[2]; bh[2*ntp+1][1] = r[3];
            }
            #pragma unroll
            for (int ntp = 0; ntp < 2; ntp++) {
                uint32_t r[4];
                ldsm4(r, uBl + b_off[ntp] + ks*2);
                bl[2*ntp][0] = r[0]; bl[2*ntp][1] = r[1];
                bl[2*ntp+1][0] = r[2]; bl[2*ntp+1][1] = r[3];
            }
            #pragma unroll
            for (int mt = 0; mt < 2; mt++) ldsm4(af[mt], uAh + a_off[mt] + ks*2);
            #pragma unroll
            for (int mt = 0; mt < 2; mt++)
                #pragma unroll
                for (int nt = 0; nt < 4; nt++) mma16816(acc[mt][nt], af[mt], bh[nt]);
            #pragma unroll
            for (int mt = 0; mt < 2; mt++)
                #pragma unroll
                for (int nt = 0; nt < 4; nt++) mma16816(acc[mt][nt], af[mt], bl[nt]);
            #pragma unroll
            for (int mt = 0; mt < 2; mt++) ldsm4(af[mt], uAl + a_off[mt] + ks*2);
            #pragma unroll
            for (int mt = 0; mt < 2; mt++)
                #pragma unroll
                for (int nt = 0; nt < 4; nt++) mma16816(acc[mt][nt], af[mt], bh[nt]);
        }
    }

    // epilogue -> g_dbl cols < 48
    int g = lane >> 2, tg = lane & 3;
    #pragma unroll
    for (int mt = 0; mt < 2; mt++) {
        #pragma unroll
        for (int nt = 0; nt < 4; nt++) {
            int gn = wn*32 + nt*8 + 2*tg;
            if (gn >= NXP) continue;
            #pragma unroll
            for (int half = 0; half < 2; half++) {
                int gm = bm + wm*32 + mt*16 + g + half*8;
                *(float2*)(g_dbl + (size_t)gm*NXP + gn) =
                    make_float2(acc[mt][nt][half*2], acc[mt][nt][half*2 + 1]);
            }
        }
    }
}

// ---------------- bf16-split mma.sync GEMM (in_proj L1 / out_proj) ----------------
// MODE 0: A = g_hh/g_hl   -> g_xraw | g_r (+bias)                (in_proj L1, K=256)
// MODE 1: A = g_xrh/g_xrl -> g_h += (+bias), + write hh/hl split (out_proj L0, K=512)
// MODE 3: same as 1 but no hh/hl write                           (out_proj L1)
template<int MODE, int K>
__global__ void __launch_bounds__(256, 2) mmagemm_k(const __nv_bfloat16* __restrict__ Wh,
                                                    const __nv_bfloat16* __restrict__ Wl,
                                                    const float* __restrict__ bias) {
    extern __shared__ char smem[];
    constexpr int ABYTES = 128*APITCH*2;
    constexpr int STAGE  = 4*ABYTES;

    const __nv_bfloat16* Agh = (MODE == 0) ? g_hh : g_xrh;
    const __nv_bfloat16* Agl = (MODE == 0) ? g_hl : g_xrl;

    int tid = threadIdx.x, wid = tid >> 5, lane = tid & 31;
    int bm = blockIdx.y * 128, bn = blockIdx.x * 128;
    int wm = wid & 1, wn = wid >> 1;

    uint32_t base = smem_u32(smem);
    int r0 = tid >> 2,         c0 = (tid & 3) << 3;
    int r1 = (tid + 256) >> 2, c1 = ((tid + 256) & 3) << 3;
    uint32_t dA0 = (uint32_t)(r0*APITCH + c0)*2, dA1 = (uint32_t)(r1*APITCH + c1)*2;

    int lr = lane & 7, sel = lane >> 3;
    uint32_t a_off[4], b_off[2];
    #pragma unroll
    for (int mt = 0; mt < 4; mt++)
        a_off[mt] = (uint32_t)(((wm*64 + mt*16 + lr + ((sel & 1) << 3))*APITCH + ((sel >> 1) << 3)) * 2);
    #pragma unroll
    for (int ntp = 0; ntp < 2; ntp++)
        b_off[ntp] = (uint32_t)(((wn*32 + ntp*16 + lr + ((sel >> 1) << 3))*APITCH + ((sel & 1) << 3)) * 2);

    float acc[4][4][4];
    #pragma unroll
    for (int mt = 0; mt < 4; mt++)
        #pragma unroll
        for (int nt = 0; nt < 4; nt++)
            #pragma unroll
            for (int q = 0; q < 4; q++) acc[mt][nt][q] = 0.f;

    const int NC = K / 32;

    auto issue = [&](int c) {
        uint32_t sb = base + (uint32_t)(c & 1)*STAGE;
        int k0 = c * 32;
        cpa16(sb + dA0,            Agh + (size_t)(bm + r0)*K + k0 + c0);
        cpa16(sb + dA1,            Agh + (size_t)(bm + r1)*K + k0 + c1);
        cpa16(sb + ABYTES + dA0,   Agl + (size_t)(bm + r0)*K + k0 + c0);
        cpa16(sb + ABYTES + dA1,   Agl + (size_t)(bm + r1)*K + k0 + c1);
        cpa16(sb + 2*ABYTES + dA0, Wh + (size_t)(bn + r0)*K + k0 + c0);
        cpa16(sb + 2*ABYTES + dA1, Wh + (size_t)(bn + r1)*K + k0 + c1);
        cpa16(sb + 3*ABYTES + dA0, Wl + (size_t)(bn + r0)*K + k0 + c0);
        cpa16(sb + 3*ABYTES + dA1, Wl + (size_t)(bn + r1)*K + k0 + c1);
        asm volatile("cp.async.commit_group;" ::: "memory");
    };

    issue(0);
    for (int c = 0; c < NC; c++) {
        if (c + 1 < NC) {
            issue(c + 1);
            asm volatile("cp.async.wait_group 1;" ::: "memory");
        } else {
            asm volatile("cp.async.wait_group 0;" ::: "memory");
        }
        __syncthreads();

        uint32_t sb  = base + (uint32_t)(c & 1)*STAGE;
        uint32_t uAh = sb, uAl = sb + ABYTES;
        uint32_t uBh = sb + 2*ABYTES, uBl = sb + 3*ABYTES;

        #pragma unroll
        for (int ks = 0; ks < 32; ks += 16) {
            uint32_t bh[4][2], bl[4][2], af[4][4];
            #pragma unroll
            for (int ntp = 0; ntp < 2; ntp++) {
                uint32_t r[4];
                ldsm4(r, uBh + b_off[ntp] + ks*2);
                bh[2*ntp][0] = r[0]; bh[2*ntp][1] = r[1];
                bh[2*ntp+1][0] = r[2]; bh[2*ntp+1][1] = r[3];
            }
            #pragma unroll
            for (int ntp = 0; ntp < 2; ntp++) {
                uint32_t r[4];
                ldsm4(r, uBl + b_off[ntp] + ks*2);
                bl[2*ntp][0] = r[0]; bl[2*ntp][1] = r[1];
                bl[2*ntp+1][0] = r[2]; bl[2*ntp+1][1] = r[3];
            }
            #pragma unroll
            for (int mt = 0; mt < 4; mt++) ldsm4(af[mt], uAh + a_off[mt] + ks*2);
            #pragma unroll
            for (int mt = 0; mt < 4; mt++)
                #pragma unroll
                for (int nt = 0; nt < 4; nt++) mma16816(acc[mt][nt], af[mt], bh[nt]);
            #pragma unroll
            for (int mt = 0; mt < 4; mt++)
                #pragma unroll
                for (int nt = 0; nt < 4; nt++) mma16816(acc[mt][nt], af[mt], bl[nt]);
            #pragma unroll
            for (int mt = 0; mt < 4; mt++) ldsm4(af[mt], uAl + a_off[mt] + ks*2);
            #pragma unroll
            for (int mt = 0; mt < 4; mt++)
                #pragma unroll
                for (int nt = 0; nt < 4; nt++) mma16816(acc[mt][nt], af[mt], bh[nt]);
        }
        __syncthreads();
    }

    int g = lane >> 2, tg = lane & 3;
    #pragma unroll
    for (int mt = 0; mt < 4; mt++) {
        #pragma unroll
        for (int nt = 0; nt < 4; nt++) {
            int gn = bn + wn*32 + nt*8 + 2*tg;
            #pragma unroll
            for (int half = 0; half < 2; half++) {
                int gm = bm + wm*64 + mt*16 + g + half*8;
                float v0 = acc[mt][nt][half*2 + 0];
                float v1 = acc[mt][nt][half*2 + 1];
                if (MODE == 0) {
                    v0 += bias[gn]; v1 += bias[gn + 1];
                    if (bn < DIi)
                        *(float2*)(g_xraw + (size_t)gm*DIi + gn) = make_float2(v0, v1);
                    else
                        *(float2*)(g_r + (size_t)gm*DIi + gn - DIi) = make_float2(v0, v1);
                } else {
                    float2 h = *(const float2*)(g_h + (size_t)gm*DD + gn);
                    h.x += v0 + bias[gn];
                    h.y += v1 + bias[gn + 1];
                    *(float2*)(g_h + (size_t)gm*DD + gn) = h;
                    if (MODE == 1) {
                        __nv_bfloat16 h0 = __float2bfloat16_rn(h.x);
                        __nv_bfloat16 h1 = __float2bfloat16_rn(h.y);
                        __nv_bfloat162 ph; ph.x = h0; ph.y = h1;
                        __nv_bfloat162 pl;
                        pl.x = __float2bfloat16_rn(h.x - __bfloat162float(h0));
                        pl.y = __float2bfloat16_rn(h.y - __bfloat162float(h1));
                        *(__nv_bfloat162*)(g_hh + (size_t)gm*DD + gn) = ph;
                        *(__nv_bfloat162*)(g_hl + (size_t)gm*DD + gn) = pl;
                    }
                }
            }
        }
    }
}

// ------- selective scan: fused conv+silu, delta, scan, D*u, silu(r) gate -------
template<int IS_L0>
__global__ __launch_bounds__(128) void scan_k(const float* __restrict__ Alog,
                                              const float* __restrict__ Dp,
                                              const float* __restrict__ dtw,
                                              const float* __restrict__ dtb,
                                              const float* __restrict__ cw,
                                              const float* __restrict__ cb,
                                              const int* __restrict__ x) {
    int b = blockIdx.x >> 2;
    int d = ((blockIdx.x & 3) << 7) + threadIdx.x;
    int tid = threadIdx.x;

    __shared__ __align__(16) float sq[2][48];

    float Av[DSs];
    bool ia = true;
    #pragma unroll
    for (int s = 0; s < DSs; s++) {
        Av[s] = -__expf(Alog[d*DSs + s]);
        ia = ia && (fabsf(Av[s] + (float)(s+1)) < 1e-4f);
    }
    float wr[DTRr];
    #pragma unroll
    for (int r2 = 0; r2 < DTRr; r2++) wr[r2] = dtw[r2*DIi + d];
    float dtb_d = dtb[d];
    float Dd = Dp[d];
    float w0 = cw[d*4 + 0], w1 = cw[d*4 + 1], w2 = cw[d*4 + 2], w3 = cw[d*4 + 3];
    float cbv = cb[d];

    float hs[DSs];
    #pragma unroll
    for (int s = 0; s < DSs; s++) hs[s] = 0.f;

    size_t tb = (size_t)b*LL;
    uint32_t sqa = smem_u32(sq);

    // prologue: q row for l=0
    if (tid < 12) cpa16(sqa + tid*16, g_dbl + tb*NXP + tid*4);
    asm volatile("cp.async.commit_group;\ncp.async.wait_group 0;" ::: "memory");
    __syncthreads();

    float ring0 = 0.f, ring1 = 0.f, ring2 = 0.f;
    float raw_n, r_n;
    int xv_nn = 0;
    if (IS_L0) {
        int xv = x[tb];
        raw_n = g_vt[xv*1024 + d];
        r_n   = g_vt[xv*1024 + 512 + d];
        xv_nn = x[tb + 1];
    } else {
        raw_n = g_xraw[tb*DIi + d];
        r_n   = g_r[tb*DIi + d];
    }

    for (int l = 0; l < LL; l++) {
        size_t t = tb + l;
        // prefetch next q row into other buffer
        if (l + 1 < LL && tid < 12)
            cpa16(sqa + ((l+1)&1)*192 + tid*16, g_dbl + (t+1)*NXP + tid*4);
        asm volatile("cp.async.commit_group;" ::: "memory");

        float raw = raw_n, rr = r_n;
        if (l + 1 < LL) {
            if (IS_L0) {
                raw_n = g_vt[xv_nn*1024 + d];
                r_n   = g_vt[xv_nn*1024 + 512 + d];
                if (l + 2 < LL) xv_nn = x[tb + l + 2];
            } else {
                raw_n = g_xraw[(t+1)*DIi + d];
                r_n   = g_r[(t+1)*DIi + d];
            }
        }

        // conv + silu
        float ua = cbv + ring0*w0 + ring1*w1 + ring2*w2 + raw*w3;
        ring0 = ring1; ring1 = ring2; ring2 = raw;
        float u = ua / (1.f + __expf(-ua));

        const float* qf = sq[l & 1];
        float xv2 = dtb_d;
        #pragma unroll
        for (int r2 = 0; r2 < DTRr; r2++) xv2 += qf[r2]*wr[r2];
        float dlt = fmaxf(xv2, 0.f) + __logf(1.f + __expf(-fabsf(xv2)));
        float du = dlt*u;

        float e[DSs];
        if (ia) {
            float p = __expf(-dlt);
            e[0] = p;
            #pragma unroll
            for (int s = 1; s < DSs; s++) e[s] = e[s>>1]*e[(s-1)>>1];
        } else {
            #pragma unroll
            for (int s = 0; s < DSs; s++) e[s] = __expf(dlt*Av[s]);
        }

        float y = 0.f;
        #pragma unroll
        for (int s = 0; s < DSs; s++) {
            hs[s] = e[s]*hs[s] + du*qf[16 + s];
            y += hs[s]*qf[32 + s];
        }
        float sg = rr / (1.f + __expf(-rr));
        float yo = (y + u*Dd)*sg;
        __nv_bfloat16 hh = __float2bfloat16_rn(yo);
        g_xrh[t*DIi + d] = hh;
        g_xrl[t*DIi + d] = __float2bfloat16_rn(yo - __bfloat162float(hh));

        asm volatile("cp.async.wait_group 0;" ::: "memory");
        __syncthreads();
    }
}

// ---------------- fused LayerNorm + mean-pool ----------------
__global__ __launch_bounds__(256) void lnpool_k(const float* __restrict__ g,
                                                const float* __restrict__ bln) {
    int b = blockIdx.x;
    int d = threadIdx.x;
    int wid = d >> 5, lane = d & 31;
    __shared__ float ws[8], wq[8];
    float acc = 0.f;
    for (int l = 0; l < LL; l++) {
        size_t t = (size_t)b*LL + l;
        float v = g_h[t*DD + d];
        float s = v, qq = v*v;
        #pragma unroll
        for (int o = 16; o > 0; o >>= 1) {
            s  += __shfl_down_sync(0xffffffffu, s, o);
            qq += __shfl_down_sync(0xffffffffu, qq, o);
        }
        if (lane == 0) { ws[wid] = s; wq[wid] = qq; }
        __syncthreads();
        float S = 0.f, Q = 0.f;
        #pragma unroll
        for (int i = 0; i < 8; i++) { S += ws[i]; Q += wq[i]; }
        float mu = S * (1.f/DD);
        float var = Q * (1.f/DD) - mu*mu;
        acc += (v - mu) * rsqrtf(var + 1e-5f);
        __syncthreads();
    }
    g_p[b*DD + d] = g[d]*acc*(1.f/LL) + bln[d];
}

// ---------------- MLP head ----------------
__global__ __launch_bounds__(128) void head_k(const float* __restrict__ w1,
                                              const float* __restrict__ b1,
                                              const float* __restrict__ w2,
                                              const float* __restrict__ b2,
                                              float* __restrict__ out) {
    int b = blockIdx.x;
    int j = threadIdx.x;
    float hsum = b1[j];
    #pragma unroll 8
    for (int d = 0; d < DD; d++) hsum += g_p[b*DD + d]*w1[d*DH + j];
    hsum = fmaxf(hsum, 0.f);
    __shared__ float s0[DH], s1[DH];
    s0[j] = hsum*w2[j*2];
    s1[j] = hsum*w2[j*2 + 1];
    __syncthreads();
    #pragma unroll
    for (int st = 64; st > 0; st >>= 1) {
        if (j < st) { s0[j] += s0[j + st]; s1[j] += s1[j + st]; }
        __syncthreads();
    }
    if (j == 0) {
        out[b*2]     = s0[0] + b2[0];
        out[b*2 + 1] = s1[0] + b2[1];
    }
}

// ---------------- launcher ----------------
extern "C" void kernel_launch(void* const* d_in, const int* in_sizes, int n_in,
                              void* d_out, int out_size) {
    const int*   x       = (const int*)  d_in[0];
    const float* emb     = (const float*)d_in[1];
    const float* in_w    = (const float*)d_in[2];
    const float* in_b    = (const float*)d_in[3];
    const float* conv_w  = (const float*)d_in[4];
    const float* conv_b  = (const float*)d_in[5];
    const float* xproj_w = (const float*)d_in[6];
    const float* dt_w    = (const float*)d_in[7];
    const float* dt_b    = (const float*)d_in[8];
    const float* A_log   = (const float*)d_in[9];
    const float* Dp      = (const float*)d_in[10];
    const float* out_w   = (const float*)d_in[11];
    const float* out_b   = (const float*)d_in[12];
    const float* ln_g    = (const float*)d_in[13];
    const float* ln_b    = (const float*)d_in[14];
    const float* w1      = (const float*)d_in[15];
    const float* b1      = (const float*)d_in[16];
    const float* w2      = (const float*)d_in[17];
    const float* b2      = (const float*)d_in[18];
    float* out = (float*)d_out;

    const int SM128 = 2 * (4*128*APITCH*2);   // 81920
    cudaFuncSetAttribute(mmagemm_k<0,256>, cudaFuncAttributeMaxDynamicSharedMemorySize, SM128);
    cudaFuncSetAttribute(mmagemm_k<1,512>, cudaFuncAttributeMaxDynamicSharedMemorySize, SM128);
    cudaFuncSetAttribute(mmagemm_k<3,512>, cudaFuncAttributeMaxDynamicSharedMemorySize, SM128);

    __nv_bfloat16 *wbh, *wbl;
    cudaGetSymbolAddress((void**)&wbh, g_wbh);
    cudaGetSymbolAddress((void**)&wbl, g_wbl);

    // launch order arranged so ncu (-s 5) profiles xproj_k<1> (6th launch)
    vt_k<<<64, 256>>>(emb, in_w, in_b);                                   // 1
    tsplit_k<<<256, 256>>>(xproj_w, wbh + WT_XP, wbl + WT_XP, NXP, 9);    // 2
    embed_k<<<(TT*DD)/256, 256>>>(x, emb);                                // 3
    tsplit_k<<<512, 256>>>(out_w, wbh + WT_OUT, wbl + WT_OUT, DD, 9);     // 4
    tsplit_k<<<1024, 256>>>(in_w + (size_t)DD*2*DIi,
                            wbh + WT_LAY + WT_IN, wbl + WT_LAY + WT_IN, 1024, 8); // 5

    // ---- layer 0 ----
    xproj_k<1><<<TT/128, 256>>>(wbh + WT_XP, wbl + WT_XP, conv_w, conv_b, x);     // 6
    scan_k<1><<<BB*4, 128>>>(A_log, Dp, dt_w, dt_b, conv_w, conv_b, x);           // 7
    mmagemm_k<1,512><<<dim3(2, TT/128), 256, SM128>>>(wbh + WT_OUT, wbl + WT_OUT, out_b); // 8

    tsplit_k<<<256, 256>>>(xproj_w + (size_t)DIi*NXP,
                           wbh + WT_LAY + WT_XP, wbl + WT_LAY + WT_XP, NXP, 9);   // 9
    tsplit_k<<<512, 256>>>(out_w + (size_t)DIi*DD,
                           wbh + WT_LAY + WT_OUT, wbl + WT_LAY + WT_OUT, DD, 9);  // 10

    // ---- layer 1 ----
    mmagemm_k<0,256><<<dim3(8, TT/128), 256, SM128>>>(
        wbh + WT_LAY + WT_IN, wbl + WT_LAY + WT_IN, in_b + 2*DIi);                // 11
    xproj_k<0><<<TT/128, 256>>>(wbh + WT_LAY + WT_XP, wbl + WT_LAY + WT_XP,
                                conv_w + DIi*DCc, conv_b + DIi, x);               // 12
    scan_k<0><<<BB*4, 128>>>(A_log + DIi*DSs, Dp + DIi,
                             dt_w + DTRr*DIi, dt_b + DIi,
                             conv_w + DIi*DCc, conv_b + DIi, x);                  // 13
    mmagemm_k<3,512><<<dim3(2, TT/128), 256, SM128>>>(
        wbh + WT_LAY + WT_OUT, wbl + WT_LAY + WT_OUT, out_b + DD);                // 14

    lnpool_k<<<BB, 256>>>(ln_g, ln_b);                                            // 15
    head_k<<<BB, DH>>>(w1, b1, w2, b2, out);                                      // 16
}